// round 10
// baseline (speedup 1.0000x reference)
#include <cuda_runtime.h>
#include <cuda_bf16.h>
#include <float.h>
#include <stdint.h>

#define HH 4
#define BB 1024
#define DQv 512
#define DFv 128
#define DD1 128
#define DD2 64

__device__ float g_Wq[HH * DQv * DD2];
__device__ float g_bq[HH * DD2];
__device__ float g_bc[HH * 128];
__device__ float g_fq[BB * HH * DD2];
// pre-split bf16 images
__device__ __nv_bfloat16 g_B0[HH * 128 * 128];   // [h][c][k]
__device__ __nv_bfloat16 g_B1[HH * 128 * 128];
__device__ __nv_bfloat16 g_B2[HH * 128 * 128];
__device__ __nv_bfloat16 g_A0[(long)BB * 200 * 128];  // [b][l][k]
__device__ __nv_bfloat16 g_A1[(long)BB * 200 * 128];
__device__ __nv_bfloat16 g_A2[(long)BB * 200 * 128];

__device__ __forceinline__ float silu_f(float x) { return __fdividef(x, 1.f + __expf(-x)); }
__device__ __forceinline__ uint32_t smem_u32(const void* p) {
    uint32_t a;
    asm("{ .reg .u64 t; cvta.to.shared.u64 t, %1; cvt.u32.u64 %0, t; }" : "=r"(a) : "l"(p));
    return a;
}
__device__ __forceinline__ uint32_t bf2pack(float lo, float hi) {
    uint32_t r;
    asm("cvt.rn.bf16x2.f32 %0, %1, %2;" : "=r"(r) : "f"(hi), "f"(lo));
    return r;
}
__device__ __forceinline__ float bflo(uint32_t q) { return __uint_as_float(q << 16); }
__device__ __forceinline__ float bfhi(uint32_t q) { return __uint_as_float(q & 0xffff0000u); }

__device__ __forceinline__ void ldm_x4(uint32_t a[4], uint32_t addr) {
    asm volatile("ldmatrix.sync.aligned.m8n8.x4.shared.b16 {%0,%1,%2,%3}, [%4];"
        : "=r"(a[0]), "=r"(a[1]), "=r"(a[2]), "=r"(a[3]) : "r"(addr));
}
__device__ __forceinline__ void ldm_x2(uint32_t b[2], uint32_t addr) {
    asm volatile("ldmatrix.sync.aligned.m8n8.x2.shared.b16 {%0,%1}, [%2];"
        : "=r"(b[0]), "=r"(b[1]) : "r"(addr));
}
__device__ __forceinline__ void mma16816(float d[4], const uint32_t a[4], const uint32_t b[2]) {
    asm volatile(
        "mma.sync.aligned.m16n8k16.row.col.f32.bf16.bf16.f32 "
        "{%0,%1,%2,%3}, {%4,%5,%6,%7}, {%8,%9}, {%0,%1,%2,%3};"
        : "+f"(d[0]), "+f"(d[1]), "+f"(d[2]), "+f"(d[3])
        : "r"(a[0]), "r"(a[1]), "r"(a[2]), "r"(a[3]), "r"(b[0]), "r"(b[1]));
}
__device__ __forceinline__ void cp16(uint32_t dst, const void* src, bool valid) {
    int n = valid ? 16 : 0;
    asm volatile("cp.async.cg.shared.global [%0], [%1], 16, %2;" :: "r"(dst), "l"(src), "r"(n));
}
#define CP_COMMIT_WAIT() do {                                   \
    asm volatile("cp.async.commit_group;" ::: "memory");        \
    asm volatile("cp.async.wait_group 0;" ::: "memory");        \
} while (0)

// ---------------- prekernels ----------------
__global__ void collapse_q_kernel(const float* __restrict__ Wq1, const float* __restrict__ bq1,
                                  const float* __restrict__ Wq2, const float* __restrict__ bq2) {
    int idx = blockIdx.x * 256 + threadIdx.x;
    int c = idx & 63, k = (idx >> 6) & 511, h = idx >> 15;
    const float* a  = Wq1 + (h * DQv + k) * DD1;
    const float* w2 = Wq2 + h * DD1 * DD2 + c;
    float acc = 0.f;
#pragma unroll 8
    for (int j = 0; j < DD1; ++j) acc += a[j] * w2[j * DD2];
    g_Wq[idx] = acc;
    if (k == 0) {
        float bb = bq2[h * DD2 + c];
        const float* b1p = bq1 + h * DD1;
#pragma unroll 8
        for (int j = 0; j < DD1; ++j) bb += b1p[j] * w2[j * DD2];
        g_bq[h * DD2 + c] = bb;
    }
}

// collapsed W^T -> bf16x3 splits, [h][c][k]
__global__ void collapse_fvT_kernel(const float* __restrict__ Wf1, const float* __restrict__ bf1,
                                    const float* __restrict__ Wf2, const float* __restrict__ bf2,
                                    const float* __restrict__ Wv1, const float* __restrict__ bv1,
                                    const float* __restrict__ Wv2, const float* __restrict__ bv2) {
    int idx = blockIdx.x * 256 + threadIdx.x;
    int c = idx & 127, k = (idx >> 7) & 127, h = idx >> 14;
    const float *W1, *W2, *B1, *B2; int cc;
    if (c < 64) { W1 = Wf1; W2 = Wf2; B1 = bf1; B2 = bf2; cc = c; }
    else        { W1 = Wv1; W2 = Wv2; B1 = bv1; B2 = bv2; cc = c - 64; }
    const float* a  = W1 + (h * DFv + k) * DD1;
    const float* w2 = W2 + h * DD1 * DD2 + cc;
    float acc = 0.f;
#pragma unroll 8
    for (int j = 0; j < DD1; ++j) acc += a[j] * w2[j * DD2];
    int o = h * 16384 + c * 128 + k;
    __nv_bfloat16 q0 = __float2bfloat16(acc);
    float r1 = acc - __bfloat162float(q0);
    __nv_bfloat16 q1 = __float2bfloat16(r1);
    float r2 = r1 - __bfloat162float(q1);
    g_B0[o] = q0; g_B1[o] = q1; g_B2[o] = __float2bfloat16(r2);
    if (k == 0) {
        float bb = B2[h * DD2 + cc];
        const float* b1p = B1 + h * DD1;
#pragma unroll 8
        for (int j = 0; j < DD1; ++j) bb += b1p[j] * w2[j * DD2];
        g_bc[h * 128 + c] = bb;
    }
}

// fact -> bf16x3 splits, [b][l][k]; each thread handles 8 consecutive elements
__global__ __launch_bounds__(256) void presplit_fact(const float* __restrict__ fact) {
    long idx = (long)blockIdx.x * 256 + threadIdx.x;   // < 3,276,800
    long base = idx * 8;
    float xv[8];
    *reinterpret_cast<float4*>(xv)     = *reinterpret_cast<const float4*>(fact + base);
    *reinterpret_cast<float4*>(xv + 4) = *reinterpret_cast<const float4*>(fact + base + 4);
    uint32_t p0[4], p1[4], p2[4];
#pragma unroll
    for (int i = 0; i < 4; ++i) {
        float lo = xv[2 * i], hi = xv[2 * i + 1];
        uint32_t q0 = bf2pack(lo, hi);
        float rlo = lo - bflo(q0), rhi = hi - bfhi(q0);
        uint32_t q1 = bf2pack(rlo, rhi);
        float slo = rlo - bflo(q1), shi = rhi - bfhi(q1);
        p0[i] = q0; p1[i] = q1; p2[i] = bf2pack(slo, shi);
    }
    *reinterpret_cast<uint4*>(reinterpret_cast<char*>(g_A0) + base * 2) = make_uint4(p0[0], p0[1], p0[2], p0[3]);
    *reinterpret_cast<uint4*>(reinterpret_cast<char*>(g_A1) + base * 2) = make_uint4(p1[0], p1[1], p1[2], p1[3]);
    *reinterpret_cast<uint4*>(reinterpret_cast<char*>(g_A2) + base * 2) = make_uint4(p2[0], p2[1], p2[2], p2[3]);
}

__global__ __launch_bounds__(256) void fq_kernel(const float* __restrict__ query) {
    __shared__ float qs[32 * 68];
    __shared__ float ws[64 * 64];
    const int tid = threadIdx.x;
    const int h  = blockIdx.x & 3;
    const int bg = blockIdx.x >> 2;
    const int bl = tid >> 3, cg = tid & 7;
    float acc[8];
#pragma unroll
    for (int j = 0; j < 8; ++j) acc[j] = 0.f;
    for (int kc = 0; kc < 8; ++kc) {
        __syncthreads();
#pragma unroll
        for (int it = 0; it < 8; ++it) {
            int idx = tid + it * 256;
            qs[(idx >> 6) * 68 + (idx & 63)] = query[(bg * 32 + (idx >> 6)) * DQv + kc * 64 + (idx & 63)];
        }
#pragma unroll
        for (int it = 0; it < 16; ++it) {
            int idx = tid + it * 256;
            ws[idx] = g_Wq[(h * DQv + kc * 64 + (idx >> 6)) * DD2 + (idx & 63)];
        }
        __syncthreads();
#pragma unroll 4
        for (int k = 0; k < 64; ++k) {
            float qv = qs[bl * 68 + k];
            float4 w01 = *reinterpret_cast<const float4*>(ws + k * 64 + cg * 8);
            float4 w23 = *reinterpret_cast<const float4*>(ws + k * 64 + cg * 8 + 4);
            acc[0] += qv * w01.x; acc[1] += qv * w01.y;
            acc[2] += qv * w01.z; acc[3] += qv * w01.w;
            acc[4] += qv * w23.x; acc[5] += qv * w23.y;
            acc[6] += qv * w23.z; acc[7] += qv * w23.w;
        }
    }
    int bglob = bg * 32 + bl;
#pragma unroll
    for (int j = 0; j < 8; ++j) {
        int c = cg * 8 + j;
        g_fq[bglob * 256 + h * 64 + c] = silu_f(acc[j] + g_bq[h * DD2 + c]);
    }
}

// ---------------- HMMA main kernel: one CTA per (b,h) ----------------
// smem: A splits 3x112x256B (XOR swizzle) | B splits 3x128x256B | scratch
#define AS_SPL 28672
#define BS_OFF 86016
#define BS_SPL 32768
#define SCR_OFF 184320
#define SMEM_BYTES 188928

template<int MT>
__device__ __forceinline__ void gemm_half(uint32_t sbase, int nb, int lane, float d[][8]) {
#pragma unroll
    for (int mt = 0; mt < MT; ++mt)
#pragma unroll
        for (int i = 0; i < 8; ++i) d[mt][i] = 0.f;

    const uint32_t xr = (uint32_t)(lane & 7);             // XOR key (constant/thread)
    const uint32_t arow = (uint32_t)((lane & 15)) * 256;  // A row byte base (tile-local)
    const uint32_t achk = (uint32_t)(lane >> 4);          // A chunk half
    const uint32_t brow0 = (uint32_t)(nb + (lane & 7)) * 256;
    const uint32_t brow1 = brow0 + 8 * 256;
    const uint32_t bchk = (uint32_t)((lane >> 3) & 1);

#pragma unroll 1
    for (int ks = 0; ks < 8; ++ks) {
        uint32_t bf[3][2][2];
        const uint32_t bx = (((uint32_t)(2 * ks) + bchk) ^ xr) * 16;
#pragma unroll
        for (int s = 0; s < 3; ++s) {
            ldm_x2(bf[s][0], sbase + BS_OFF + s * BS_SPL + brow0 + bx);
            ldm_x2(bf[s][1], sbase + BS_OFF + s * BS_SPL + brow1 + bx);
        }
        const uint32_t ax = (((uint32_t)(2 * ks) + achk) ^ xr) * 16;
#pragma unroll
        for (int mt = 0; mt < MT; ++mt) {
            const uint32_t aoff = arow + (uint32_t)(mt * 16) * 256 + ax;
            uint32_t a0[4], a1[4], a2[4];
            ldm_x4(a0, sbase + aoff);
            ldm_x4(a1, sbase + AS_SPL + aoff);
            ldm_x4(a2, sbase + 2 * AS_SPL + aoff);
            mma16816(d[mt],     a0, bf[0][0]); mma16816(d[mt] + 4, a0, bf[0][1]);
            mma16816(d[mt],     a0, bf[1][0]); mma16816(d[mt] + 4, a0, bf[1][1]);
            mma16816(d[mt],     a0, bf[2][0]); mma16816(d[mt] + 4, a0, bf[2][1]);
            mma16816(d[mt],     a1, bf[0][0]); mma16816(d[mt] + 4, a1, bf[0][1]);
            mma16816(d[mt],     a1, bf[1][0]); mma16816(d[mt] + 4, a1, bf[1][1]);
            mma16816(d[mt],     a2, bf[0][0]); mma16816(d[mt] + 4, a2, bf[0][1]);
        }
    }
}

__global__ __launch_bounds__(256, 1) void mha_hmma_kernel(
    const int* __restrict__ mask, const float* __restrict__ mm,
    const float* __restrict__ tau1, const float* __restrict__ tau2,
    float* __restrict__ out)
{
    extern __shared__ char smem[];
    float* pdw = reinterpret_cast<float*>(smem + SCR_OFF);  // [4][224]
    float* alf = pdw + 4 * 224;                             // [224]
    float* msc = alf + 224;                                 // [32]

    const int tid  = threadIdx.x;
    const int w    = tid >> 5;
    const int lane = tid & 31;
    const int g    = lane >> 2;
    const int t4   = lane & 3;
    const int b = blockIdx.x >> 2;
    const int h = blockIdx.x & 3;
    const int nb = w * 16;
    const bool is_f = (w < 4);
    const uint32_t sbase = smem_u32(smem);

    const int c0 = nb + t4 * 2, c1 = c0 + 1, c2 = c0 + 8, c3 = c0 + 9;
    const float bc0 = g_bc[h * 128 + c0], bc1 = g_bc[h * 128 + c1];
    const float bc2 = g_bc[h * 128 + c2], bc3 = g_bc[h * 128 + c3];
    float fq0 = 0.f, fq1 = 0.f, fq2 = 0.f, fq3 = 0.f;
    if (is_f) {
        fq0 = g_fq[b * 256 + h * 64 + c0]; fq1 = g_fq[b * 256 + h * 64 + c1];
        fq2 = g_fq[b * 256 + h * 64 + c2]; fq3 = g_fq[b * 256 + h * 64 + c3];
    }

    // ---- stage B splits + A half0 via cp.async ----
    {
        const __nv_bfloat16* bsrc[3] = {g_B0 + h * 16384, g_B1 + h * 16384, g_B2 + h * 16384};
#pragma unroll
        for (int it = 0; it < 24; ++it) {
            int idx = tid + it * 256;          // < 6144
            int s = idx >> 11, r = idx & 2047;
            int crow = r >> 4, c = r & 15;
            uint32_t dst = sbase + BS_OFF + s * BS_SPL + crow * 256 + ((c ^ (crow & 7)) * 16);
            cp16(dst, bsrc[s] + crow * 128 + c * 8, true);
        }
        const __nv_bfloat16* asrc[3] = {g_A0 + (long)b * 25600, g_A1 + (long)b * 25600, g_A2 + (long)b * 25600};
#pragma unroll
        for (int it = 0; it < 21; ++it) {
            int idx = tid + it * 256;          // < 5376
            int s = idx / 1792, r = idx % 1792;
            int l = r >> 4, c = r & 15;
            uint32_t dst = sbase + s * AS_SPL + l * 256 + ((c ^ (l & 7)) * 16);
            cp16(dst, asrc[s] + l * 128 + c * 8, true);
        }
        CP_COMMIT_WAIT();
    }
    __syncthreads();

    // ---- half0 GEMM (rows 0..111) ----
    float d0[7][8];
    gemm_half<7>(sbase, nb, lane, d0);

    if (is_f) {
#pragma unroll
        for (int mt = 0; mt < 7; ++mt) {
            float s0 = silu_f(d0[mt][0] + bc0) * fq0 + silu_f(d0[mt][1] + bc1) * fq1
                     + silu_f(d0[mt][4] + bc2) * fq2 + silu_f(d0[mt][5] + bc3) * fq3;
            float s1 = silu_f(d0[mt][2] + bc0) * fq0 + silu_f(d0[mt][3] + bc1) * fq1
                     + silu_f(d0[mt][6] + bc2) * fq2 + silu_f(d0[mt][7] + bc3) * fq3;
            s0 += __shfl_xor_sync(0xffffffffu, s0, 1); s0 += __shfl_xor_sync(0xffffffffu, s0, 2);
            s1 += __shfl_xor_sync(0xffffffffu, s1, 1); s1 += __shfl_xor_sync(0xffffffffu, s1, 2);
            if (t4 == 0) {
                pdw[w * 224 + mt * 16 + g]     = s0;
                pdw[w * 224 + mt * 16 + g + 8] = s1;
            }
        }
    }
    __syncthreads();   // half0 A reads done everywhere

    // ---- stage A half1 (rows 112..207; >=200 zero-filled) ----
    {
        const __nv_bfloat16* asrc[3] = {g_A0 + (long)b * 25600, g_A1 + (long)b * 25600, g_A2 + (long)b * 25600};
#pragma unroll
        for (int it = 0; it < 18; ++it) {
            int idx = tid + it * 256;          // < 4608
            int s = idx / 1536, r = idx % 1536;
            int l = r >> 4, c = r & 15;        // l: 0..95 -> global 112+l
            int lg = 112 + l;
            uint32_t dst = sbase + s * AS_SPL + l * 256 + ((c ^ (l & 7)) * 16);
            cp16(dst, asrc[s] + lg * 128 + c * 8, lg < 200);
        }
        CP_COMMIT_WAIT();
    }
    __syncthreads();

    // ---- half1 GEMM (rows 112..207) ----
    float d1[6][8];
    gemm_half<6>(sbase, nb, lane, d1);

    if (is_f) {
#pragma unroll
        for (int mt = 0; mt < 6; ++mt) {
            float s0 = silu_f(d1[mt][0] + bc0) * fq0 + silu_f(d1[mt][1] + bc1) * fq1
                     + silu_f(d1[mt][4] + bc2) * fq2 + silu_f(d1[mt][5] + bc3) * fq3;
            float s1 = silu_f(d1[mt][2] + bc0) * fq0 + silu_f(d1[mt][3] + bc1) * fq1
                     + silu_f(d1[mt][6] + bc2) * fq2 + silu_f(d1[mt][7] + bc3) * fq3;
            s0 += __shfl_xor_sync(0xffffffffu, s0, 1); s0 += __shfl_xor_sync(0xffffffffu, s0, 2);
            s1 += __shfl_xor_sync(0xffffffffu, s1, 1); s1 += __shfl_xor_sync(0xffffffffu, s1, 2);
            if (t4 == 0) {
                pdw[w * 224 + 112 + mt * 16 + g]     = s0;
                pdw[w * 224 + 112 + mt * 16 + g + 8] = s1;
            }
        }
    }
    __syncthreads();

    // ---- logits ----
    const float t1a = tau1[h], t1b = tau1[4 + h];
    const float cb1v = tau2[h], cb2v = tau2[4 + h], cb3v = tau2[8 + h];
    if (tid < 200) {
        float dd = pdw[tid] + pdw[224 + tid] + pdw[448 + tid] + pdw[672 + tid];
        float mk = (float)mask[b * 200 + tid];
        dd += (-1e9f) * (1.f - mk);                 // mask BEFORE cosine mix
        float bias = mm[b * 200 + tid] / t1a + mm[204800 + b * 200 + tid] / t1b;
        alf[tid] = cb1v * dd + cb2v * bias + cb3v * dd * bias;
    }
    __syncthreads();

    // ---- softmax over 200 ----
    float v = (tid < 200) ? alf[tid] : -3.0e38f;
    float mxv = v;
#pragma unroll
    for (int off = 16; off > 0; off >>= 1) mxv = fmaxf(mxv, __shfl_xor_sync(0xffffffffu, mxv, off));
    if (lane == 0) msc[w] = mxv;
    __syncthreads();
    if (tid == 0) {
        float m = msc[0];
#pragma unroll
        for (int i = 1; i < 8; ++i) m = fmaxf(m, msc[i]);
        msc[8] = m;
    }
    __syncthreads();
    float e = (tid < 200) ? expf(v - msc[8]) : 0.f;
    float se = e;
#pragma unroll
    for (int off = 16; off > 0; off >>= 1) se += __shfl_xor_sync(0xffffffffu, se, off);
    if (lane == 0) msc[16 + w] = se;
    __syncthreads();
    if (tid == 0) {
        float s = 0.f;
#pragma unroll
        for (int i = 0; i < 8; ++i) s += msc[16 + i];
        msc[9] = __fdividef(1.f, s);
    }
    __syncthreads();
    if (tid < 200) alf[tid] = e * msc[9];
    __syncthreads();

    // ---- v-warps: alpha-weighted reduce + 1e-7 * plain sum ----
    if (!is_f) {
        float o[4] = {0.f, 0.f, 0.f, 0.f}, pp[4] = {0.f, 0.f, 0.f, 0.f};
#pragma unroll
        for (int mt = 0; mt < 7; ++mt) {
            int l0 = mt * 16 + g, l1 = l0 + 8;
            {
                float a = alf[l0];
                float s0 = silu_f(d0[mt][0] + bc0), s1 = silu_f(d0[mt][1] + bc1);
                float s2 = silu_f(d0[mt][4] + bc2), s3 = silu_f(d0[mt][5] + bc3);
                o[0] += a * s0; o[1] += a * s1; o[2] += a * s2; o[3] += a * s3;
                pp[0] += s0; pp[1] += s1; pp[2] += s2; pp[3] += s3;
            }
            {
                float a = alf[l1];
                float s0 = silu_f(d0[mt][2] + bc0), s1 = silu_f(d0[mt][3] + bc1);
                float s2 = silu_f(d0[mt][6] + bc2), s3 = silu_f(d0[mt][7] + bc3);
                o[0] += a * s0; o[1] += a * s1; o[2] += a * s2; o[3] += a * s3;
                pp[0] += s0; pp[1] += s1; pp[2] += s2; pp[3] += s3;
            }
        }
#pragma unroll
        for (int mt = 0; mt < 6; ++mt) {
            int l0 = 112 + mt * 16 + g, l1 = l0 + 8;
            if (l0 < 200) {
                float a = alf[l0];
                float s0 = silu_f(d1[mt][0] + bc0), s1 = silu_f(d1[mt][1] + bc1);
                float s2 = silu_f(d1[mt][4] + bc2), s3 = silu_f(d1[mt][5] + bc3);
                o[0] += a * s0; o[1] += a * s1; o[2] += a * s2; o[3] += a * s3;
                pp[0] += s0; pp[1] += s1; pp[2] += s2; pp[3] += s3;
            }
            if (l1 < 200) {
                float a = alf[l1];
                float s0 = silu_f(d1[mt][2] + bc0), s1 = silu_f(d1[mt][3] + bc1);
                float s2 = silu_f(d1[mt][6] + bc2), s3 = silu_f(d1[mt][7] + bc3);
                o[0] += a * s0; o[1] += a * s1; o[2] += a * s2; o[3] += a * s3;
                pp[0] += s0; pp[1] += s1; pp[2] += s2; pp[3] += s3;
            }
        }
#pragma unroll
        for (int i = 0; i < 4; ++i) {
#pragma unroll
            for (int off = 4; off < 32; off <<= 1) {
                o[i]  += __shfl_xor_sync(0xffffffffu, o[i],  off);
                pp[i] += __shfl_xor_sync(0xffffffffu, pp[i], off);
            }
        }
        if (lane < 4) {
            int cv = nb - 64 + lane * 2;
            out[b * 256 + h * 64 + cv]     = o[0] + 1e-7f * pp[0];
            out[b * 256 + h * 64 + cv + 1] = o[1] + 1e-7f * pp[1];
            out[b * 256 + h * 64 + cv + 8] = o[2] + 1e-7f * pp[2];
            out[b * 256 + h * 64 + cv + 9] = o[3] + 1e-7f * pp[3];
        }
    }
}

extern "C" void kernel_launch(void* const* d_in, const int* in_sizes, int n_in,
                              void* d_out, int out_size) {
    const float* query = (const float*)d_in[0];
    const float* fact  = (const float*)d_in[1];
    const int*   mask  = (const int*)  d_in[2];
    const float* mm    = (const float*)d_in[3];
    const float* Wq1   = (const float*)d_in[4];
    const float* bq1   = (const float*)d_in[5];
    const float* Wq2   = (const float*)d_in[6];
    const float* bq2   = (const float*)d_in[7];
    const float* Wf1   = (const float*)d_in[8];
    const float* bf1   = (const float*)d_in[9];
    const float* Wf2   = (const float*)d_in[10];
    const float* bf2   = (const float*)d_in[11];
    const float* Wv1   = (const float*)d_in[12];
    const float* bv1   = (const float*)d_in[13];
    const float* Wv2   = (const float*)d_in[14];
    const float* bv2   = (const float*)d_in[15];
    const float* tau1  = (const float*)d_in[16];
    const float* tau2  = (const float*)d_in[17];
    float* out = (float*)d_out;

    cudaFuncSetAttribute(mha_hmma_kernel, cudaFuncAttributeMaxDynamicSharedMemorySize, SMEM_BYTES);

    collapse_q_kernel<<<512, 256>>>(Wq1, bq1, Wq2, bq2);
    collapse_fvT_kernel<<<256, 256>>>(Wf1, bf1, Wf2, bf2, Wv1, bv1, Wv2, bv2);
    presplit_fact<<<12800, 256>>>(fact);
    fq_kernel<<<128, 256>>>(query);
    mha_hmma_kernel<<<BB * HH, 256, SMEM_BYTES>>>(mask, mm, tau1, tau2, out);
}

// round 11
// speedup vs baseline: 1.0061x; 1.0061x over previous
#include <cuda_runtime.h>
#include <cuda_bf16.h>
#include <float.h>
#include <stdint.h>

#define HH 4
#define BB 1024
#define DQv 512
#define DFv 128
#define DD1 128
#define DD2 64

__device__ float g_Wq[HH * DQv * DD2];
__device__ float g_bq[HH * DD2];
__device__ float g_bc[HH * 128];
__device__ float g_fq[BB * HH * DD2];
__device__ __nv_bfloat16 g_B0[HH * 128 * 128];   // [h][c][k]
__device__ __nv_bfloat16 g_B1[HH * 128 * 128];
__device__ __nv_bfloat16 g_B2[HH * 128 * 128];
__device__ __nv_bfloat16 g_A0[(long)BB * 200 * 128];  // [b][l][k]
__device__ __nv_bfloat16 g_A1[(long)BB * 200 * 128];
__device__ __nv_bfloat16 g_A2[(long)BB * 200 * 128];

__device__ __forceinline__ float silu_f(float x) { return __fdividef(x, 1.f + __expf(-x)); }
__device__ __forceinline__ uint32_t smem_u32(const void* p) {
    uint32_t a;
    asm("{ .reg .u64 t; cvta.to.shared.u64 t, %1; cvt.u32.u64 %0, t; }" : "=r"(a) : "l"(p));
    return a;
}
__device__ __forceinline__ uint32_t bf2pack(float lo, float hi) {
    uint32_t r;
    asm("cvt.rn.bf16x2.f32 %0, %1, %2;" : "=r"(r) : "f"(hi), "f"(lo));
    return r;
}
__device__ __forceinline__ float bflo(uint32_t q) { return __uint_as_float(q << 16); }
__device__ __forceinline__ float bfhi(uint32_t q) { return __uint_as_float(q & 0xffff0000u); }

__device__ __forceinline__ void ldm_x4(uint32_t a[4], uint32_t addr) {
    asm volatile("ldmatrix.sync.aligned.m8n8.x4.shared.b16 {%0,%1,%2,%3}, [%4];"
        : "=r"(a[0]), "=r"(a[1]), "=r"(a[2]), "=r"(a[3]) : "r"(addr));
}
__device__ __forceinline__ void ldm_x2(uint32_t b[2], uint32_t addr) {
    asm volatile("ldmatrix.sync.aligned.m8n8.x2.shared.b16 {%0,%1}, [%2];"
        : "=r"(b[0]), "=r"(b[1]) : "r"(addr));
}
__device__ __forceinline__ void mma16816(float d[4], const uint32_t a[4], const uint32_t b[2]) {
    asm volatile(
        "mma.sync.aligned.m16n8k16.row.col.f32.bf16.bf16.f32 "
        "{%0,%1,%2,%3}, {%4,%5,%6,%7}, {%8,%9}, {%0,%1,%2,%3};"
        : "+f"(d[0]), "+f"(d[1]), "+f"(d[2]), "+f"(d[3])
        : "r"(a[0]), "r"(a[1]), "r"(a[2]), "r"(a[3]), "r"(b[0]), "r"(b[1]));
}
__device__ __forceinline__ void cp16(uint32_t dst, const void* src, bool valid) {
    int n = valid ? 16 : 0;
    asm volatile("cp.async.cg.shared.global [%0], [%1], 16, %2;" :: "r"(dst), "l"(src), "r"(n));
}
#define CP_COMMIT()      asm volatile("cp.async.commit_group;" ::: "memory")
#define CP_WAIT0()       asm volatile("cp.async.wait_group 0;" ::: "memory")

// ---------------- prekernels ----------------
__global__ void collapse_q_kernel(const float* __restrict__ Wq1, const float* __restrict__ bq1,
                                  const float* __restrict__ Wq2, const float* __restrict__ bq2) {
    int idx = blockIdx.x * 256 + threadIdx.x;
    int c = idx & 63, k = (idx >> 6) & 511, h = idx >> 15;
    const float* a  = Wq1 + (h * DQv + k) * DD1;
    const float* w2 = Wq2 + h * DD1 * DD2 + c;
    float acc = 0.f;
#pragma unroll 8
    for (int j = 0; j < DD1; ++j) acc += a[j] * w2[j * DD2];
    g_Wq[idx] = acc;
    if (k == 0) {
        float bb = bq2[h * DD2 + c];
        const float* b1p = bq1 + h * DD1;
#pragma unroll 8
        for (int j = 0; j < DD1; ++j) bb += b1p[j] * w2[j * DD2];
        g_bq[h * DD2 + c] = bb;
    }
}

__global__ void collapse_fvT_kernel(const float* __restrict__ Wf1, const float* __restrict__ bf1,
                                    const float* __restrict__ Wf2, const float* __restrict__ bf2,
                                    const float* __restrict__ Wv1, const float* __restrict__ bv1,
                                    const float* __restrict__ Wv2, const float* __restrict__ bv2) {
    int idx = blockIdx.x * 256 + threadIdx.x;
    int c = idx & 127, k = (idx >> 7) & 127, h = idx >> 14;
    const float *W1, *W2, *B1, *B2; int cc;
    if (c < 64) { W1 = Wf1; W2 = Wf2; B1 = bf1; B2 = bf2; cc = c; }
    else        { W1 = Wv1; W2 = Wv2; B1 = bv1; B2 = bv2; cc = c - 64; }
    const float* a  = W1 + (h * DFv + k) * DD1;
    const float* w2 = W2 + h * DD1 * DD2 + cc;
    float acc = 0.f;
#pragma unroll 8
    for (int j = 0; j < DD1; ++j) acc += a[j] * w2[j * DD2];
    int o = h * 16384 + c * 128 + k;
    __nv_bfloat16 q0 = __float2bfloat16(acc);
    float r1 = acc - __bfloat162float(q0);
    __nv_bfloat16 q1 = __float2bfloat16(r1);
    float r2 = r1 - __bfloat162float(q1);
    g_B0[o] = q0; g_B1[o] = q1; g_B2[o] = __float2bfloat16(r2);
    if (k == 0) {
        float bb = B2[h * DD2 + cc];
        const float* b1p = B1 + h * DD1;
#pragma unroll 8
        for (int j = 0; j < DD1; ++j) bb += b1p[j] * w2[j * DD2];
        g_bc[h * 128 + c] = bb;
    }
}

__global__ __launch_bounds__(256) void presplit_fact(const float* __restrict__ fact) {
    long idx = (long)blockIdx.x * 256 + threadIdx.x;
    long base = idx * 8;
    float xv[8];
    *reinterpret_cast<float4*>(xv)     = *reinterpret_cast<const float4*>(fact + base);
    *reinterpret_cast<float4*>(xv + 4) = *reinterpret_cast<const float4*>(fact + base + 4);
    uint32_t p0[4], p1[4], p2[4];
#pragma unroll
    for (int i = 0; i < 4; ++i) {
        float lo = xv[2 * i], hi = xv[2 * i + 1];
        uint32_t q0 = bf2pack(lo, hi);
        float rlo = lo - bflo(q0), rhi = hi - bfhi(q0);
        uint32_t q1 = bf2pack(rlo, rhi);
        float slo = rlo - bflo(q1), shi = rhi - bfhi(q1);
        p0[i] = q0; p1[i] = q1; p2[i] = bf2pack(slo, shi);
    }
    *reinterpret_cast<uint4*>(reinterpret_cast<char*>(g_A0) + base * 2) = make_uint4(p0[0], p0[1], p0[2], p0[3]);
    *reinterpret_cast<uint4*>(reinterpret_cast<char*>(g_A1) + base * 2) = make_uint4(p1[0], p1[1], p1[2], p1[3]);
    *reinterpret_cast<uint4*>(reinterpret_cast<char*>(g_A2) + base * 2) = make_uint4(p2[0], p2[1], p2[2], p2[3]);
}

// fq: grid 512 (128 bg x 4 h), each block: 8 b x 64 c
__global__ __launch_bounds__(256) void fq_kernel(const float* __restrict__ query) {
    __shared__ float qs[8 * 66];
    __shared__ float ws[64 * 64];
    const int tid = threadIdx.x;
    const int h  = blockIdx.x & 3;
    const int bg = blockIdx.x >> 2;
    const int bl = tid >> 5;           // warp id = local b
    const int cw = tid & 31;           // 2 cols
    float acc0 = 0.f, acc1 = 0.f;
    for (int kc = 0; kc < 8; ++kc) {
        __syncthreads();
        {
            int bb = tid >> 5, kk = tid & 31;
            float2 q2 = *reinterpret_cast<const float2*>(query + (long)(bg * 8 + bb) * DQv + kc * 64 + kk * 2);
            qs[bb * 66 + kk * 2]     = q2.x;
            qs[bb * 66 + kk * 2 + 1] = q2.y;
        }
#pragma unroll
        for (int it = 0; it < 16; ++it) {
            int idx = tid + it * 256;
            ws[idx] = g_Wq[(h * DQv + kc * 64 + (idx >> 6)) * DD2 + (idx & 63)];
        }
        __syncthreads();
#pragma unroll 4
        for (int k = 0; k < 64; ++k) {
            float qv = qs[bl * 66 + k];
            float2 w2 = *reinterpret_cast<const float2*>(ws + k * 64 + cw * 2);
            acc0 += qv * w2.x;
            acc1 += qv * w2.y;
        }
    }
    int bglob = bg * 8 + bl;
    int c = cw * 2;
    g_fq[bglob * 256 + h * 64 + c]     = silu_f(acc0 + g_bq[h * DD2 + c]);
    g_fq[bglob * 256 + h * 64 + c + 1] = silu_f(acc1 + g_bq[h * DD2 + c + 1]);
}

// ---------------- HMMA main kernel: one CTA per (b,h) ----------------
// 8 warps = 4 ng (n32 col groups) x 2 mg (m halves of the staged tile).
#define AS_SPL 28672
#define BS_OFF 86016
#define BS_SPL 32768
#define SCR_OFF 184320
#define SMEM_BYTES 188032

template<int MT>
__device__ __forceinline__ void gemm32(uint32_t sbase, int nb, int mbase, int lane, float d[][16]) {
#pragma unroll
    for (int mt = 0; mt < MT; ++mt)
#pragma unroll
        for (int i = 0; i < 16; ++i) d[mt][i] = 0.f;

    const uint32_t xr = (uint32_t)(lane & 7);
    const uint32_t arow = (uint32_t)(mbase + (lane & 15)) * 256;
    const uint32_t achk = (uint32_t)(lane >> 4);
    const uint32_t bl7 = (uint32_t)(lane & 7);
    const uint32_t bchk = (uint32_t)((lane >> 3) & 1);

#pragma unroll 1
    for (int ks = 0; ks < 8; ++ks) {
        uint32_t bf[3][4][2];
        const uint32_t bx = (((uint32_t)(2 * ks) + bchk) ^ xr) * 16;
#pragma unroll
        for (int s = 0; s < 3; ++s)
#pragma unroll
            for (int j = 0; j < 4; ++j)
                ldm_x2(bf[s][j], sbase + BS_OFF + s * BS_SPL + (uint32_t)(nb + j * 8 + bl7) * 256 + bx);
        const uint32_t ax = (((uint32_t)(2 * ks) + achk) ^ xr) * 16;
#pragma unroll
        for (int mt = 0; mt < MT; ++mt) {
            const uint32_t aoff = arow + (uint32_t)(mt * 16) * 256 + ax;
            uint32_t a0[4], a1[4], a2[4];
            ldm_x4(a0, sbase + aoff);
            ldm_x4(a1, sbase + AS_SPL + aoff);
            ldm_x4(a2, sbase + 2 * AS_SPL + aoff);
#pragma unroll
            for (int j = 0; j < 4; ++j) {
                mma16816(d[mt] + 4 * j, a0, bf[0][j]);
                mma16816(d[mt] + 4 * j, a0, bf[1][j]);
                mma16816(d[mt] + 4 * j, a0, bf[2][j]);
                mma16816(d[mt] + 4 * j, a1, bf[0][j]);
                mma16816(d[mt] + 4 * j, a1, bf[1][j]);
                mma16816(d[mt] + 4 * j, a2, bf[0][j]);
            }
        }
    }
}

__global__ __launch_bounds__(256, 1) void mha_hmma_kernel(
    const int* __restrict__ mask, const float* __restrict__ mm,
    const float* __restrict__ tau1, const float* __restrict__ tau2,
    float* __restrict__ out)
{
    extern __shared__ char smem[];
    float* pdw = reinterpret_cast<float*>(smem + SCR_OFF);  // [2][208]
    float* alf = pdw + 416;                                 // [208]
    float* msc = alf + 208;                                 // [32]
    float* vo  = msc + 32;                                  // [2][64]
    float* vp  = vo + 128;                                  // [2][64]

    const int tid  = threadIdx.x;
    const int w    = tid >> 5;
    const int lane = tid & 31;
    const int g    = lane >> 2;
    const int t4   = lane & 3;
    const int b = blockIdx.x >> 2;
    const int h = blockIdx.x & 3;
    const int ng = w & 3;            // n32 group
    const int mg = w >> 2;           // m half
    const int nb = ng * 32;
    const bool is_f = (ng < 2);
    const uint32_t sbase = smem_u32(smem);

    // thread's 8 columns: nb + j*8 + t4*2 (+1), j=0..3
    float bcv[8], fqv[8];
#pragma unroll
    for (int j = 0; j < 4; ++j) {
        int c = nb + j * 8 + t4 * 2;
        bcv[2 * j]     = g_bc[h * 128 + c];
        bcv[2 * j + 1] = g_bc[h * 128 + c + 1];
        if (is_f) {
            fqv[2 * j]     = g_fq[b * 256 + h * 64 + c];
            fqv[2 * j + 1] = g_fq[b * 256 + h * 64 + c + 1];
        } else { fqv[2 * j] = 0.f; fqv[2 * j + 1] = 0.f; }
    }

    // ---- stage B splits + A half0 (rows 0..111) ----
    {
        const __nv_bfloat16* bsrc[3] = {g_B0 + h * 16384, g_B1 + h * 16384, g_B2 + h * 16384};
#pragma unroll
        for (int it = 0; it < 24; ++it) {
            int idx = tid + it * 256;
            int s = idx >> 11, r = idx & 2047;
            int crow = r >> 4, c = r & 15;
            uint32_t dst = sbase + BS_OFF + s * BS_SPL + crow * 256 + ((c ^ (crow & 7)) * 16);
            cp16(dst, bsrc[s] + crow * 128 + c * 8, true);
        }
        const __nv_bfloat16* asrc[3] = {g_A0 + (long)b * 25600, g_A1 + (long)b * 25600, g_A2 + (long)b * 25600};
#pragma unroll
        for (int it = 0; it < 21; ++it) {
            int idx = tid + it * 256;
            int s = idx / 1792, r = idx % 1792;
            int l = r >> 4, c = r & 15;
            uint32_t dst = sbase + s * AS_SPL + l * 256 + ((c ^ (l & 7)) * 16);
            cp16(dst, asrc[s] + l * 128 + c * 8, true);
        }
        CP_COMMIT(); CP_WAIT0();
    }
    __syncthreads();

    // ---- half0 GEMM: mg0 rows 0..63 (MT=4), mg1 rows 64..111 (MT=3) ----
    float d0[4][16];
    if (mg == 0) gemm32<4>(sbase, nb, 0, lane, d0);
    else         gemm32<3>(sbase, nb, 64, lane, d0);
    __syncthreads();   // all warps done reading A half0

    // ---- issue A half1 staging (rows 112..207), overlap with epilogue ----
    {
        const __nv_bfloat16* asrc[3] = {g_A0 + (long)b * 25600, g_A1 + (long)b * 25600, g_A2 + (long)b * 25600};
#pragma unroll
        for (int it = 0; it < 18; ++it) {
            int idx = tid + it * 256;
            int s = idx / 1536, r = idx % 1536;
            int l = r >> 4, c = r & 15;
            int lg = 112 + l;
            uint32_t dst = sbase + s * AS_SPL + l * 256 + ((c ^ (l & 7)) * 16);
            cp16(dst, asrc[s] + (long)lg * 128 + c * 8, lg < 200);
        }
        CP_COMMIT();
    }

    // ---- f epilogue half0 ----
    const int MT0 = (mg == 0) ? 4 : 3;
    const int row0 = (mg == 0) ? 0 : 64;
    if (is_f) {
#pragma unroll
        for (int mt = 0; mt < 4; ++mt) {
            if (mt < MT0) {
                float s0 = 0.f, s1 = 0.f;
#pragma unroll
                for (int j = 0; j < 4; ++j) {
                    s0 += silu_f(d0[mt][4*j]   + bcv[2*j])   * fqv[2*j]
                        + silu_f(d0[mt][4*j+1] + bcv[2*j+1]) * fqv[2*j+1];
                    s1 += silu_f(d0[mt][4*j+2] + bcv[2*j])   * fqv[2*j]
                        + silu_f(d0[mt][4*j+3] + bcv[2*j+1]) * fqv[2*j+1];
                }
                s0 += __shfl_xor_sync(0xffffffffu, s0, 1); s0 += __shfl_xor_sync(0xffffffffu, s0, 2);
                s1 += __shfl_xor_sync(0xffffffffu, s1, 1); s1 += __shfl_xor_sync(0xffffffffu, s1, 2);
                if (t4 == 0) {
                    pdw[ng * 208 + row0 + mt * 16 + g]     = s0;
                    pdw[ng * 208 + row0 + mt * 16 + g + 8] = s1;
                }
            }
        }
    }
    CP_WAIT0();
    __syncthreads();   // half1 A staged; pdw half0 visible

    // ---- half1 GEMM: mg0 local rows 0..47 (gl 112+), mg1 local 48..95 (gl 160+) ----
    float d1[3][16];
    if (mg == 0) gemm32<3>(sbase, nb, 0, lane, d1);
    else         gemm32<3>(sbase, nb, 48, lane, d1);

    const int row1 = (mg == 0) ? 112 : 160;
    if (is_f) {
#pragma unroll
        for (int mt = 0; mt < 3; ++mt) {
            float s0 = 0.f, s1 = 0.f;
#pragma unroll
            for (int j = 0; j < 4; ++j) {
                s0 += silu_f(d1[mt][4*j]   + bcv[2*j])   * fqv[2*j]
                    + silu_f(d1[mt][4*j+1] + bcv[2*j+1]) * fqv[2*j+1];
                s1 += silu_f(d1[mt][4*j+2] + bcv[2*j])   * fqv[2*j]
                    + silu_f(d1[mt][4*j+3] + bcv[2*j+1]) * fqv[2*j+1];
            }
            s0 += __shfl_xor_sync(0xffffffffu, s0, 1); s0 += __shfl_xor_sync(0xffffffffu, s0, 2);
            s1 += __shfl_xor_sync(0xffffffffu, s1, 1); s1 += __shfl_xor_sync(0xffffffffu, s1, 2);
            int l0 = row1 + mt * 16 + g;
            if (t4 == 0) {
                pdw[ng * 208 + l0] = s0;
                if (l0 + 8 < 200) pdw[ng * 208 + l0 + 8] = s1;
            }
        }
    }
    __syncthreads();

    // ---- logits ----
    const float t1a = tau1[h], t1b = tau1[4 + h];
    const float cb1v = tau2[h], cb2v = tau2[4 + h], cb3v = tau2[8 + h];
    if (tid < 200) {
        float dd = pdw[tid] + pdw[208 + tid];
        float mk = (float)mask[b * 200 + tid];
        dd += (-1e9f) * (1.f - mk);                 // mask BEFORE cosine mix
        float bias = mm[b * 200 + tid] / t1a + mm[204800 + b * 200 + tid] / t1b;
        alf[tid] = cb1v * dd + cb2v * bias + cb3v * dd * bias;
    }
    __syncthreads();

    // ---- softmax over 200 ----
    float v = (tid < 200) ? alf[tid] : -3.0e38f;
    float mxv = v;
#pragma unroll
    for (int off = 16; off > 0; off >>= 1) mxv = fmaxf(mxv, __shfl_xor_sync(0xffffffffu, mxv, off));
    if (lane == 0) msc[w] = mxv;
    __syncthreads();
    if (tid == 0) {
        float m = msc[0];
#pragma unroll
        for (int i = 1; i < 8; ++i) m = fmaxf(m, msc[i]);
        msc[8] = m;
    }
    __syncthreads();
    float e = (tid < 200) ? expf(v - msc[8]) : 0.f;
    float se = e;
#pragma unroll
    for (int off = 16; off > 0; off >>= 1) se += __shfl_xor_sync(0xffffffffu, se, off);
    if (lane == 0) msc[16 + w] = se;
    __syncthreads();
    if (tid == 0) {
        float s = 0.f;
#pragma unroll
        for (int i = 0; i < 8; ++i) s += msc[16 + i];
        msc[9] = __fdividef(1.f, s);
    }
    __syncthreads();
    if (tid < 200) alf[tid] = e * msc[9];
    __syncthreads();

    // ---- v-warps: alpha-weighted + plain sums over own rows ----
    if (!is_f) {
        float o[8], pp[8];
#pragma unroll
        for (int i = 0; i < 8; ++i) { o[i] = 0.f; pp[i] = 0.f; }
#pragma unroll
        for (int mt = 0; mt < 4; ++mt) {
            if (mt < MT0) {
                int l0 = row0 + mt * 16 + g;
                float a0 = alf[l0], a1 = alf[l0 + 8];
#pragma unroll
                for (int j = 0; j < 4; ++j) {
                    float s00 = silu_f(d0[mt][4*j]   + bcv[2*j]);
                    float s01 = silu_f(d0[mt][4*j+1] + bcv[2*j+1]);
                    float s10 = silu_f(d0[mt][4*j+2] + bcv[2*j]);
                    float s11 = silu_f(d0[mt][4*j+3] + bcv[2*j+1]);
                    o[2*j]   += a0 * s00 + a1 * s10;  pp[2*j]   += s00 + s10;
                    o[2*j+1] += a0 * s01 + a1 * s11;  pp[2*j+1] += s01 + s11;
                }
            }
        }
#pragma unroll
        for (int mt = 0; mt < 3; ++mt) {
            int l0 = row1 + mt * 16 + g;
            int l1 = l0 + 8;
            float a0 = alf[l0];
            float a1 = (l1 < 200) ? alf[l1] : 0.f;
            bool v1 = (l1 < 200);
#pragma unroll
            for (int j = 0; j < 4; ++j) {
                float s00 = silu_f(d1[mt][4*j]   + bcv[2*j]);
                float s01 = silu_f(d1[mt][4*j+1] + bcv[2*j+1]);
                float s10 = v1 ? silu_f(d1[mt][4*j+2] + bcv[2*j])   : 0.f;
                float s11 = v1 ? silu_f(d1[mt][4*j+3] + bcv[2*j+1]) : 0.f;
                o[2*j]   += a0 * s00 + a1 * s10;  pp[2*j]   += s00 + s10;
                o[2*j+1] += a0 * s01 + a1 * s11;  pp[2*j+1] += s01 + s11;
            }
        }
#pragma unroll
        for (int i = 0; i < 8; ++i) {
#pragma unroll
            for (int off = 4; off < 32; off <<= 1) {
                o[i]  += __shfl_xor_sync(0xffffffffu, o[i],  off);
                pp[i] += __shfl_xor_sync(0xffffffffu, pp[i], off);
            }
        }
        if (lane < 4) {
            int vb = (ng - 2) * 32;
#pragma unroll
            for (int j = 0; j < 4; ++j) {
                int cv = vb + j * 8 + t4 * 2;
                vo[mg * 64 + cv]     = o[2*j];
                vo[mg * 64 + cv + 1] = o[2*j+1];
                vp[mg * 64 + cv]     = pp[2*j];
                vp[mg * 64 + cv + 1] = pp[2*j+1];
            }
        }
    }
    __syncthreads();

    if (tid < 64) {
        out[b * 256 + h * 64 + tid] =
            (vo[tid] + vo[64 + tid]) + 1e-7f * (vp[tid] + vp[64 + tid]);
    }
}

extern "C" void kernel_launch(void* const* d_in, const int* in_sizes, int n_in,
                              void* d_out, int out_size) {
    const float* query = (const float*)d_in[0];
    const float* fact  = (const float*)d_in[1];
    const int*   mask  = (const int*)  d_in[2];
    const float* mm    = (const float*)d_in[3];
    const float* Wq1   = (const float*)d_in[4];
    const float* bq1   = (const float*)d_in[5];
    const float* Wq2   = (const float*)d_in[6];
    const float* bq2   = (const float*)d_in[7];
    const float* Wf1   = (const float*)d_in[8];
    const float* bf1   = (const float*)d_in[9];
    const float* Wf2   = (const float*)d_in[10];
    const float* bf2   = (const float*)d_in[11];
    const float* Wv1   = (const float*)d_in[12];
    const float* bv1   = (const float*)d_in[13];
    const float* Wv2   = (const float*)d_in[14];
    const float* bv2   = (const float*)d_in[15];
    const float* tau1  = (const float*)d_in[16];
    const float* tau2  = (const float*)d_in[17];
    float* out = (float*)d_out;

    cudaFuncSetAttribute(mha_hmma_kernel, cudaFuncAttributeMaxDynamicSharedMemorySize, SMEM_BYTES);

    collapse_q_kernel<<<512, 256>>>(Wq1, bq1, Wq2, bq2);
    collapse_fvT_kernel<<<256, 256>>>(Wf1, bf1, Wf2, bf2, Wv1, bv1, Wv2, bv2);
    presplit_fact<<<12800, 256>>>(fact);
    fq_kernel<<<512, 256>>>(query);
    mha_hmma_kernel<<<BB * HH, 256, SMEM_BYTES>>>(mask, mm, tau1, tau2, out);
}

// round 12
// speedup vs baseline: 1.4581x; 1.4493x over previous
#include <cuda_runtime.h>
#include <cuda_bf16.h>
#include <float.h>
#include <stdint.h>

#define HH 4
#define BB 1024
#define DQv 512
#define DFv 128
#define DD1 128
#define DD2 64

__device__ float g_Wq[HH * DQv * DD2];
__device__ float g_bq[HH * DD2];
__device__ float g_bc[HH * 128];
__device__ float g_fq[BB * HH * DD2];
__device__ __nv_bfloat16 g_B0[HH * 128 * 128];   // [h][c][k]
__device__ __nv_bfloat16 g_B1[HH * 128 * 128];
__device__ __nv_bfloat16 g_A0[(long)BB * 200 * 128];  // [b][l][k]
__device__ __nv_bfloat16 g_A1[(long)BB * 200 * 128];

__device__ __forceinline__ float silu_f(float x) { return __fdividef(x, 1.f + __expf(-x)); }
__device__ __forceinline__ uint32_t smem_u32(const void* p) {
    uint32_t a;
    asm("{ .reg .u64 t; cvta.to.shared.u64 t, %1; cvt.u32.u64 %0, t; }" : "=r"(a) : "l"(p));
    return a;
}
__device__ __forceinline__ uint32_t bf2pack(float lo, float hi) {
    uint32_t r;
    asm("cvt.rn.bf16x2.f32 %0, %1, %2;" : "=r"(r) : "f"(hi), "f"(lo));
    return r;
}
__device__ __forceinline__ float bflo(uint32_t q) { return __uint_as_float(q << 16); }
__device__ __forceinline__ float bfhi(uint32_t q) { return __uint_as_float(q & 0xffff0000u); }

__device__ __forceinline__ void ldm_x4(uint32_t a[4], uint32_t addr) {
    asm volatile("ldmatrix.sync.aligned.m8n8.x4.shared.b16 {%0,%1,%2,%3}, [%4];"
        : "=r"(a[0]), "=r"(a[1]), "=r"(a[2]), "=r"(a[3]) : "r"(addr));
}
__device__ __forceinline__ void ldm_x2(uint32_t b[2], uint32_t addr) {
    asm volatile("ldmatrix.sync.aligned.m8n8.x2.shared.b16 {%0,%1}, [%2];"
        : "=r"(b[0]), "=r"(b[1]) : "r"(addr));
}
__device__ __forceinline__ void mma16816(float d[4], const uint32_t a[4], const uint32_t b[2]) {
    asm volatile(
        "mma.sync.aligned.m16n8k16.row.col.f32.bf16.bf16.f32 "
        "{%0,%1,%2,%3}, {%4,%5,%6,%7}, {%8,%9}, {%0,%1,%2,%3};"
        : "+f"(d[0]), "+f"(d[1]), "+f"(d[2]), "+f"(d[3])
        : "r"(a[0]), "r"(a[1]), "r"(a[2]), "r"(a[3]), "r"(b[0]), "r"(b[1]));
}
__device__ __forceinline__ void cp16(uint32_t dst, const void* src) {
    asm volatile("cp.async.cg.shared.global [%0], [%1], 16;" :: "r"(dst), "l"(src));
}
#define CP_COMMIT()      asm volatile("cp.async.commit_group;" ::: "memory")
#define CP_WAIT0()       asm volatile("cp.async.wait_group 0;" ::: "memory")

// ---------------- prekernels ----------------
__global__ void collapse_q_kernel(const float* __restrict__ Wq1, const float* __restrict__ bq1,
                                  const float* __restrict__ Wq2, const float* __restrict__ bq2) {
    int idx = blockIdx.x * 256 + threadIdx.x;
    int c = idx & 63, k = (idx >> 6) & 511, h = idx >> 15;
    const float* a  = Wq1 + (h * DQv + k) * DD1;
    const float* w2 = Wq2 + h * DD1 * DD2 + c;
    float acc = 0.f;
#pragma unroll 8
    for (int j = 0; j < DD1; ++j) acc += a[j] * w2[j * DD2];
    g_Wq[idx] = acc;
    if (k == 0) {
        float bb = bq2[h * DD2 + c];
        const float* b1p = bq1 + h * DD1;
#pragma unroll 8
        for (int j = 0; j < DD1; ++j) bb += b1p[j] * w2[j * DD2];
        g_bq[h * DD2 + c] = bb;
    }
}

__global__ void collapse_fvT_kernel(const float* __restrict__ Wf1, const float* __restrict__ bf1,
                                    const float* __restrict__ Wf2, const float* __restrict__ bf2,
                                    const float* __restrict__ Wv1, const float* __restrict__ bv1,
                                    const float* __restrict__ Wv2, const float* __restrict__ bv2) {
    int idx = blockIdx.x * 256 + threadIdx.x;
    int c = idx & 127, k = (idx >> 7) & 127, h = idx >> 14;
    const float *W1, *W2, *B1, *B2; int cc;
    if (c < 64) { W1 = Wf1; W2 = Wf2; B1 = bf1; B2 = bf2; cc = c; }
    else        { W1 = Wv1; W2 = Wv2; B1 = bv1; B2 = bv2; cc = c - 64; }
    const float* a  = W1 + (h * DFv + k) * DD1;
    const float* w2 = W2 + h * DD1 * DD2 + cc;
    float acc = 0.f;
#pragma unroll 8
    for (int j = 0; j < DD1; ++j) acc += a[j] * w2[j * DD2];
    int o = h * 16384 + c * 128 + k;
    __nv_bfloat16 q0 = __float2bfloat16(acc);
    float r1 = acc - __bfloat162float(q0);
    g_B0[o] = q0; g_B1[o] = __float2bfloat16(r1);
    if (k == 0) {
        float bb = B2[h * DD2 + cc];
        const float* b1p = B1 + h * DD1;
#pragma unroll 8
        for (int j = 0; j < DD1; ++j) bb += b1p[j] * w2[j * DD2];
        g_bc[h * 128 + c] = bb;
    }
}

__global__ __launch_bounds__(256) void presplit_fact(const float* __restrict__ fact) {
    long idx = (long)blockIdx.x * 256 + threadIdx.x;
    long base = idx * 8;
    float xv[8];
    *reinterpret_cast<float4*>(xv)     = *reinterpret_cast<const float4*>(fact + base);
    *reinterpret_cast<float4*>(xv + 4) = *reinterpret_cast<const float4*>(fact + base + 4);
    uint32_t p0[4], p1[4];
#pragma unroll
    for (int i = 0; i < 4; ++i) {
        float lo = xv[2 * i], hi = xv[2 * i + 1];
        uint32_t q0 = bf2pack(lo, hi);
        float rlo = lo - bflo(q0), rhi = hi - bfhi(q0);
        p0[i] = q0; p1[i] = bf2pack(rlo, rhi);
    }
    *reinterpret_cast<uint4*>(reinterpret_cast<char*>(g_A0) + base * 2) = make_uint4(p0[0], p0[1], p0[2], p0[3]);
    *reinterpret_cast<uint4*>(reinterpret_cast<char*>(g_A1) + base * 2) = make_uint4(p1[0], p1[1], p1[2], p1[3]);
}

__global__ __launch_bounds__(256) void fq_kernel(const float* __restrict__ query) {
    __shared__ float qs[8 * 66];
    __shared__ float ws[64 * 64];
    const int tid = threadIdx.x;
    const int h  = blockIdx.x & 3;
    const int bg = blockIdx.x >> 2;
    const int bl = tid >> 5;
    const int cw = tid & 31;
    float acc0 = 0.f, acc1 = 0.f;
    for (int kc = 0; kc < 8; ++kc) {
        __syncthreads();
        {
            int bb = tid >> 5, kk = tid & 31;
            float2 q2 = *reinterpret_cast<const float2*>(query + (long)(bg * 8 + bb) * DQv + kc * 64 + kk * 2);
            qs[bb * 66 + kk * 2]     = q2.x;
            qs[bb * 66 + kk * 2 + 1] = q2.y;
        }
#pragma unroll
        for (int it = 0; it < 16; ++it) {
            int idx = tid + it * 256;
            ws[idx] = g_Wq[(h * DQv + kc * 64 + (idx >> 6)) * DD2 + (idx & 63)];
        }
        __syncthreads();
#pragma unroll 4
        for (int k = 0; k < 64; ++k) {
            float qv = qs[bl * 66 + k];
            float2 w2 = *reinterpret_cast<const float2*>(ws + k * 64 + cw * 2);
            acc0 += qv * w2.x;
            acc1 += qv * w2.y;
        }
    }
    int bglob = bg * 8 + bl;
    int c = cw * 2;
    g_fq[bglob * 256 + h * 64 + c]     = silu_f(acc0 + g_bq[h * DD2 + c]);
    g_fq[bglob * 256 + h * 64 + c + 1] = silu_f(acc1 + g_bq[h * DD2 + c + 1]);
}

// ---------------- HMMA main kernel: one CTA per (b,h), 2 CTAs/SM ----------------
// bf16x2 split, 4 passes (a0b0,a0b1,a1b0,a1b1) = exact (a0+a1)(b0+b1).
// A tiled 80/80/40 rows; online softmax in v-warps; 8 warps = 4 ng(n32) x 2 mg.
#define AS_SPL 20480
#define BS_OFF 40960
#define BS_SPL 32768
#define SCR_OFF 106496
#define SMEM_BYTES 108544

template<int MT>
__device__ __forceinline__ void gemm32(uint32_t sbase, int nb, int mbase, int lane, float d[][16]) {
#pragma unroll
    for (int mt = 0; mt < MT; ++mt)
#pragma unroll
        for (int i = 0; i < 16; ++i) d[mt][i] = 0.f;

    const uint32_t xr = (uint32_t)(lane & 7);
    const uint32_t arow = (uint32_t)(mbase + (lane & 15)) * 256;
    const uint32_t achk = (uint32_t)(lane >> 4);
    const uint32_t bl7 = (uint32_t)(lane & 7);
    const uint32_t bchk = (uint32_t)((lane >> 3) & 1);

#pragma unroll 1
    for (int ks = 0; ks < 8; ++ks) {
        uint32_t bf[2][4][2];
        const uint32_t bx = (((uint32_t)(2 * ks) + bchk) ^ xr) * 16;
#pragma unroll
        for (int s = 0; s < 2; ++s)
#pragma unroll
            for (int j = 0; j < 4; ++j)
                ldm_x2(bf[s][j], sbase + BS_OFF + s * BS_SPL + (uint32_t)(nb + j * 8 + bl7) * 256 + bx);
        const uint32_t ax = (((uint32_t)(2 * ks) + achk) ^ xr) * 16;
#pragma unroll
        for (int mt = 0; mt < MT; ++mt) {
            const uint32_t aoff = arow + (uint32_t)(mt * 16) * 256 + ax;
            uint32_t a0[4], a1[4];
            ldm_x4(a0, sbase + aoff);
            ldm_x4(a1, sbase + AS_SPL + aoff);
#pragma unroll
            for (int j = 0; j < 4; ++j) {
                mma16816(d[mt] + 4 * j, a0, bf[0][j]);
                mma16816(d[mt] + 4 * j, a0, bf[1][j]);
                mma16816(d[mt] + 4 * j, a1, bf[0][j]);
                mma16816(d[mt] + 4 * j, a1, bf[1][j]);
            }
        }
    }
}

__global__ __launch_bounds__(256, 2) void mha_hmma_kernel(
    const int* __restrict__ mask, const float* __restrict__ mm,
    const float* __restrict__ tau1, const float* __restrict__ tau2,
    float* __restrict__ out)
{
    extern __shared__ char smem[];
    float* scr = reinterpret_cast<float*>(smem + SCR_OFF);
    float* pd0 = scr;          // [80]
    float* pd1 = scr + 80;     // [80]
    float* lg_s = scr + 160;   // [80]
    float* mo  = scr + 240;    // [2][64]
    float* mp  = scr + 368;    // [2][64]
    float* mS  = scr + 496;    // [4]: m0,m1,S0,S1

    const int tid  = threadIdx.x;
    const int w    = tid >> 5;
    const int lane = tid & 31;
    const int g    = lane >> 2;
    const int t4   = lane & 3;
    const int b = blockIdx.x >> 2;
    const int h = blockIdx.x & 3;
    const int ng = w & 3;
    const int mg = w >> 2;
    const int nb = ng * 32;
    const bool is_f = (ng < 2);
    const uint32_t sbase = smem_u32(smem);

    float bcv[8], fqv[8];
#pragma unroll
    for (int j = 0; j < 4; ++j) {
        int c = nb + j * 8 + t4 * 2;
        bcv[2 * j]     = g_bc[h * 128 + c];
        bcv[2 * j + 1] = g_bc[h * 128 + c + 1];
        if (is_f) {
            fqv[2 * j]     = g_fq[b * 256 + h * 64 + c];
            fqv[2 * j + 1] = g_fq[b * 256 + h * 64 + c + 1];
        } else { fqv[2 * j] = 0.f; fqv[2 * j + 1] = 0.f; }
    }

    const __nv_bfloat16* asrc0 = g_A0 + (long)b * 25600;
    const __nv_bfloat16* asrc1 = g_A1 + (long)b * 25600;

    // ---- stage B (both splits) + A tile0 (80 rows) ----
    {
        const __nv_bfloat16* bsrc[2] = {g_B0 + h * 16384, g_B1 + h * 16384};
#pragma unroll
        for (int it = 0; it < 16; ++it) {
            int idx = tid + it * 256;          // < 4096
            int s = idx >> 11, r = idx & 2047;
            int crow = r >> 4, c = r & 15;
            uint32_t dst = sbase + BS_OFF + s * BS_SPL + crow * 256 + ((c ^ (crow & 7)) * 16);
            cp16(dst, bsrc[s] + crow * 128 + c * 8);
        }
#pragma unroll
        for (int it = 0; it < 10; ++it) {
            int idx = tid + it * 256;          // < 2560
            int s = idx >> 10 >= 1 ? 1 : 0;    // idx/1280
            s = idx / 1280;
            int r = idx - s * 1280;
            int l = r >> 4, c = r & 15;
            uint32_t dst = sbase + s * AS_SPL + l * 256 + ((c ^ (l & 7)) * 16);
            const __nv_bfloat16* src = (s == 0 ? asrc0 : asrc1) + (long)l * 128 + c * 8;
            cp16(dst, src);
        }
        CP_COMMIT(); CP_WAIT0();
    }
    __syncthreads();

    const float t1a = tau1[h], t1b = tau1[4 + h];
    const float cb1v = tau2[h], cb2v = tau2[4 + h], cb3v = tau2[8 + h];

    // online softmax state (v-warps)
    float m_run = -FLT_MAX, S_run = 0.f;
    float ov[8], pv[8];
#pragma unroll
    for (int i = 0; i < 8; ++i) { ov[i] = 0.f; pv[i] = 0.f; }

#pragma unroll 1
    for (int t = 0; t < 3; ++t) {
        const int tbase = t * 80;
        const int rowbase = (t < 2) ? (mg ? 48 : 0) : (mg ? 32 : 0);
        const int MT = (t < 2) ? (mg ? 2 : 3) : (mg ? 1 : 2);
        const int rows_t = (t < 2) ? 80 : 40;

        float d[3][16];
        if (t < 2) { if (mg == 0) gemm32<3>(sbase, nb, rowbase, lane, d);
                     else         gemm32<2>(sbase, nb, rowbase, lane, d); }
        else       { if (mg == 0) gemm32<2>(sbase, nb, rowbase, lane, d);
                     else         gemm32<1>(sbase, nb, rowbase, lane, d); }

        // f epilogue: dot partials for this warp's rows
        if (is_f) {
#pragma unroll
            for (int mt = 0; mt < 3; ++mt) {
                if (mt < MT) {
                    float s0 = 0.f, s1 = 0.f;
#pragma unroll
                    for (int j = 0; j < 4; ++j) {
                        s0 += silu_f(d[mt][4*j]   + bcv[2*j])   * fqv[2*j]
                            + silu_f(d[mt][4*j+1] + bcv[2*j+1]) * fqv[2*j+1];
                        s1 += silu_f(d[mt][4*j+2] + bcv[2*j])   * fqv[2*j]
                            + silu_f(d[mt][4*j+3] + bcv[2*j+1]) * fqv[2*j+1];
                    }
                    s0 += __shfl_xor_sync(0xffffffffu, s0, 1); s0 += __shfl_xor_sync(0xffffffffu, s0, 2);
                    s1 += __shfl_xor_sync(0xffffffffu, s1, 1); s1 += __shfl_xor_sync(0xffffffffu, s1, 2);
                    if (t4 == 0) {
                        float* pdp = (ng == 0) ? pd0 : pd1;
                        pdp[rowbase + mt * 16 + g]     = s0;
                        pdp[rowbase + mt * 16 + g + 8] = s1;
                    }
                }
            }
        }
        __syncthreads();   // A(t) fully consumed; pd visible

        // prefetch A(t+1)
        if (t < 2) {
            const int ntb = tbase + 80;
            const int R = (t == 0) ? 80 : 40;
            const int chunks = R * 16;
            for (int idx = tid; idx < 2 * chunks; idx += 256) {
                int s = idx / chunks;
                int r = idx - s * chunks;
                int l = r >> 4, c = r & 15;
                uint32_t dst = sbase + s * AS_SPL + l * 256 + ((c ^ (l & 7)) * 16);
                const __nv_bfloat16* src = (s == 0 ? asrc0 : asrc1) + (long)(ntb + l) * 128 + c * 8;
                cp16(dst, src);
            }
            CP_COMMIT();
        }

        // logits for this tile
        if (tid < rows_t) {
            int l = tbase + tid;
            float dd = pd0[tid] + pd1[tid];
            float mk = (float)mask[b * 200 + l];
            dd += (-1e9f) * (1.f - mk);
            float bias = mm[b * 200 + l] / t1a + mm[204800 + b * 200 + l] / t1b;
            lg_s[tid] = cb1v * dd + cb2v * bias + cb3v * dd * bias;
        }
        __syncthreads();   // lg ready

        // v-warps: online softmax accumulate
        if (!is_f) {
#pragma unroll
            for (int mt = 0; mt < 3; ++mt) {
                if (mt < MT) {
                    int loc0 = rowbase + mt * 16 + g;
#pragma unroll
                    for (int half = 0; half < 2; ++half) {
                        int loc = loc0 + half * 8;
                        int l = tbase + loc;
                        if (l < 200) {
                            float lg = lg_s[loc];
                            float mn = fmaxf(m_run, lg);
                            float sc = __expf(m_run - mn);
                            float e  = __expf(lg - mn);
                            S_run = S_run * sc + e;
#pragma unroll
                            for (int j = 0; j < 4; ++j) {
                                float v0 = silu_f(d[mt][4*j + 2*half]     + bcv[2*j]);
                                float v1 = silu_f(d[mt][4*j + 2*half + 1] + bcv[2*j+1]);
                                ov[2*j]   = ov[2*j]   * sc + e * v0;  pv[2*j]   += v0;
                                ov[2*j+1] = ov[2*j+1] * sc + e * v1;  pv[2*j+1] += v1;
                            }
                            m_run = mn;
                        }
                    }
                }
            }
        }
        if (t < 2) CP_WAIT0();
        __syncthreads();   // lg consumed; A(t+1) staged
    }

    // ---- merge: intra-warp across g (shfl), then across mg (smem) ----
    if (!is_f) {
#pragma unroll
        for (int off = 4; off <= 16; off <<= 1) {
            float m2 = __shfl_xor_sync(0xffffffffu, m_run, off);
            float S2 = __shfl_xor_sync(0xffffffffu, S_run, off);
            float M = fmaxf(m_run, m2);
            float sa = __expf(m_run - M), sb = __expf(m2 - M);
            S_run = S_run * sa + S2 * sb;
#pragma unroll
            for (int i = 0; i < 8; ++i) {
                float o2 = __shfl_xor_sync(0xffffffffu, ov[i], off);
                float p2 = __shfl_xor_sync(0xffffffffu, pv[i], off);
                ov[i] = ov[i] * sa + o2 * sb;
                pv[i] += p2;
            }
            m_run = M;
        }
        if (lane < 4) {
#pragma unroll
            for (int j = 0; j < 4; ++j) {
                int c = (ng - 2) * 32 + j * 8 + t4 * 2;
                mo[mg * 64 + c]     = ov[2*j];
                mo[mg * 64 + c + 1] = ov[2*j+1];
                mp[mg * 64 + c]     = pv[2*j];
                mp[mg * 64 + c + 1] = pv[2*j+1];
            }
            if (ng == 2 && lane == 0) { mS[mg] = m_run; mS[2 + mg] = S_run; }
        }
    }
    __syncthreads();

    if (tid < 64) {
        float m0 = mS[0], m1 = mS[1];
        float M = fmaxf(m0, m1);
        float e0 = __expf(m0 - M), e1 = __expf(m1 - M);
        float S = mS[2] * e0 + mS[3] * e1;
        float o = mo[tid] * e0 + mo[64 + tid] * e1;
        float p = mp[tid] + mp[64 + tid];
        out[b * 256 + h * 64 + tid] = __fdividef(o, S) + 1e-7f * p;
    }
}

extern "C" void kernel_launch(void* const* d_in, const int* in_sizes, int n_in,
                              void* d_out, int out_size) {
    const float* query = (const float*)d_in[0];
    const float* fact  = (const float*)d_in[1];
    const int*   mask  = (const int*)  d_in[2];
    const float* mm    = (const float*)d_in[3];
    const float* Wq1   = (const float*)d_in[4];
    const float* bq1   = (const float*)d_in[5];
    const float* Wq2   = (const float*)d_in[6];
    const float* bq2   = (const float*)d_in[7];
    const float* Wf1   = (const float*)d_in[8];
    const float* bf1   = (const float*)d_in[9];
    const float* Wf2   = (const float*)d_in[10];
    const float* bf2   = (const float*)d_in[11];
    const float* Wv1   = (const float*)d_in[12];
    const float* bv1   = (const float*)d_in[13];
    const float* Wv2   = (const float*)d_in[14];
    const float* bv2   = (const float*)d_in[15];
    const float* tau1  = (const float*)d_in[16];
    const float* tau2  = (const float*)d_in[17];
    float* out = (float*)d_out;

    cudaFuncSetAttribute(mha_hmma_kernel, cudaFuncAttributeMaxDynamicSharedMemorySize, SMEM_BYTES);

    collapse_q_kernel<<<512, 256>>>(Wq1, bq1, Wq2, bq2);
    collapse_fvT_kernel<<<256, 256>>>(Wf1, bf1, Wf2, bf2, Wv1, bv1, Wv2, bv2);
    presplit_fact<<<12800, 256>>>(fact);
    fq_kernel<<<512, 256>>>(query);
    mha_hmma_kernel<<<BB * HH, 256, SMEM_BYTES>>>(mask, mm, tau1, tau2, out);
}

// round 13
// speedup vs baseline: 1.5793x; 1.0832x over previous
#include <cuda_runtime.h>
#include <cuda_bf16.h>
#include <float.h>
#include <stdint.h>

#define HH 4
#define BB 1024
#define DQv 512
#define DFv 128
#define DD1 128
#define DD2 64

__device__ float g_Wq[HH * DQv * DD2];
__device__ float g_bq[HH * DD2];
__device__ float g_bc[HH * 128];
__device__ float g_fq[BB * HH * DD2];
__device__ __nv_bfloat16 g_B0[HH * 128 * 128];   // [h][c][k]
__device__ __nv_bfloat16 g_B1[HH * 128 * 128];
__device__ __nv_bfloat16 g_A0[(long)BB * 200 * 128];  // [b][l][k]
__device__ __nv_bfloat16 g_A1[(long)BB * 200 * 128];

__device__ __forceinline__ float silu_f(float x) { return __fdividef(x, 1.f + __expf(-x)); }
__device__ __forceinline__ uint32_t smem_u32(const void* p) {
    uint32_t a;
    asm("{ .reg .u64 t; cvta.to.shared.u64 t, %1; cvt.u32.u64 %0, t; }" : "=r"(a) : "l"(p));
    return a;
}
__device__ __forceinline__ uint32_t bf2pack(float lo, float hi) {
    uint32_t r;
    asm("cvt.rn.bf16x2.f32 %0, %1, %2;" : "=r"(r) : "f"(hi), "f"(lo));
    return r;
}
__device__ __forceinline__ float bflo(uint32_t q) { return __uint_as_float(q << 16); }
__device__ __forceinline__ float bfhi(uint32_t q) { return __uint_as_float(q & 0xffff0000u); }

__device__ __forceinline__ void ldm_x4(uint32_t a[4], uint32_t addr) {
    asm volatile("ldmatrix.sync.aligned.m8n8.x4.shared.b16 {%0,%1,%2,%3}, [%4];"
        : "=r"(a[0]), "=r"(a[1]), "=r"(a[2]), "=r"(a[3]) : "r"(addr));
}
__device__ __forceinline__ void ldm_x2(uint32_t b[2], uint32_t addr) {
    asm volatile("ldmatrix.sync.aligned.m8n8.x2.shared.b16 {%0,%1}, [%2];"
        : "=r"(b[0]), "=r"(b[1]) : "r"(addr));
}
__device__ __forceinline__ void mma16816(float d[4], const uint32_t a[4], const uint32_t b[2]) {
    asm volatile(
        "mma.sync.aligned.m16n8k16.row.col.f32.bf16.bf16.f32 "
        "{%0,%1,%2,%3}, {%4,%5,%6,%7}, {%8,%9}, {%0,%1,%2,%3};"
        : "+f"(d[0]), "+f"(d[1]), "+f"(d[2]), "+f"(d[3])
        : "r"(a[0]), "r"(a[1]), "r"(a[2]), "r"(a[3]), "r"(b[0]), "r"(b[1]));
}
__device__ __forceinline__ void cp16(uint32_t dst, const void* src) {
    asm volatile("cp.async.cg.shared.global [%0], [%1], 16;" :: "r"(dst), "l"(src));
}
#define CP_COMMIT()      asm volatile("cp.async.commit_group;" ::: "memory")
#define CP_WAIT0()       asm volatile("cp.async.wait_group 0;" ::: "memory")

// ---------------- prekernels ----------------
__global__ void collapse_q_kernel(const float* __restrict__ Wq1, const float* __restrict__ bq1,
                                  const float* __restrict__ Wq2, const float* __restrict__ bq2) {
    int idx = blockIdx.x * 256 + threadIdx.x;
    int c = idx & 63, k = (idx >> 6) & 511, h = idx >> 15;
    const float* a  = Wq1 + (h * DQv + k) * DD1;
    const float* w2 = Wq2 + h * DD1 * DD2 + c;
    float acc = 0.f;
#pragma unroll 8
    for (int j = 0; j < DD1; ++j) acc += a[j] * w2[j * DD2];
    g_Wq[idx] = acc;
    if (k == 0) {
        float bb = bq2[h * DD2 + c];
        const float* b1p = bq1 + h * DD1;
#pragma unroll 8
        for (int j = 0; j < DD1; ++j) bb += b1p[j] * w2[j * DD2];
        g_bq[h * DD2 + c] = bb;
    }
}

__global__ void collapse_fvT_kernel(const float* __restrict__ Wf1, const float* __restrict__ bf1,
                                    const float* __restrict__ Wf2, const float* __restrict__ bf2,
                                    const float* __restrict__ Wv1, const float* __restrict__ bv1,
                                    const float* __restrict__ Wv2, const float* __restrict__ bv2) {
    int idx = blockIdx.x * 256 + threadIdx.x;
    int c = idx & 127, k = (idx >> 7) & 127, h = idx >> 14;
    const float *W1, *W2, *B1, *B2; int cc;
    if (c < 64) { W1 = Wf1; W2 = Wf2; B1 = bf1; B2 = bf2; cc = c; }
    else        { W1 = Wv1; W2 = Wv2; B1 = bv1; B2 = bv2; cc = c - 64; }
    const float* a  = W1 + (h * DFv + k) * DD1;
    const float* w2 = W2 + h * DD1 * DD2 + cc;
    float acc = 0.f;
#pragma unroll 8
    for (int j = 0; j < DD1; ++j) acc += a[j] * w2[j * DD2];
    int o = h * 16384 + c * 128 + k;
    __nv_bfloat16 q0 = __float2bfloat16(acc);
    float r1 = acc - __bfloat162float(q0);
    g_B0[o] = q0; g_B1[o] = __float2bfloat16(r1);
    if (k == 0) {
        float bb = B2[h * DD2 + cc];
        const float* b1p = B1 + h * DD1;
#pragma unroll 8
        for (int j = 0; j < DD1; ++j) bb += b1p[j] * w2[j * DD2];
        g_bc[h * 128 + c] = bb;
    }
}

__global__ __launch_bounds__(256) void presplit_fact(const float* __restrict__ fact) {
    long idx = (long)blockIdx.x * 256 + threadIdx.x;
    long base = idx * 8;
    float xv[8];
    *reinterpret_cast<float4*>(xv)     = *reinterpret_cast<const float4*>(fact + base);
    *reinterpret_cast<float4*>(xv + 4) = *reinterpret_cast<const float4*>(fact + base + 4);
    uint32_t p0[4], p1[4];
#pragma unroll
    for (int i = 0; i < 4; ++i) {
        float lo = xv[2 * i], hi = xv[2 * i + 1];
        uint32_t q0 = bf2pack(lo, hi);
        float rlo = lo - bflo(q0), rhi = hi - bfhi(q0);
        p0[i] = q0; p1[i] = bf2pack(rlo, rhi);
    }
    *reinterpret_cast<uint4*>(reinterpret_cast<char*>(g_A0) + base * 2) = make_uint4(p0[0], p0[1], p0[2], p0[3]);
    *reinterpret_cast<uint4*>(reinterpret_cast<char*>(g_A1) + base * 2) = make_uint4(p1[0], p1[1], p1[2], p1[3]);
}

// fq: grid 256 (64 bg x 4 h); block: 16 b x 16 cthreads x 4 cols
__global__ __launch_bounds__(256) void fq_kernel(const float* __restrict__ query) {
    __shared__ float qs[16 * 66];
    __shared__ float ws[64 * 64];
    const int tid = threadIdx.x;
    const int h  = blockIdx.x & 3;
    const int bg = blockIdx.x >> 2;
    const int bl = tid >> 4;
    const int cq = (tid & 15) * 4;
    float acc[4] = {0.f, 0.f, 0.f, 0.f};
    for (int kc = 0; kc < 8; ++kc) {
        __syncthreads();
#pragma unroll
        for (int it = 0; it < 4; ++it) {
            int idx = tid + it * 256;          // < 1024
            int bb = idx >> 6, kk = idx & 63;
            qs[bb * 66 + kk] = query[(long)(bg * 16 + bb) * DQv + kc * 64 + kk];
        }
#pragma unroll
        for (int it = 0; it < 16; ++it) {
            int idx = tid + it * 256;
            ws[idx] = g_Wq[(h * DQv + kc * 64 + (idx >> 6)) * DD2 + (idx & 63)];
        }
        __syncthreads();
#pragma unroll 4
        for (int k = 0; k < 64; ++k) {
            float qv = qs[bl * 66 + k];
            float4 w4 = *reinterpret_cast<const float4*>(ws + k * 64 + cq);
            acc[0] += qv * w4.x; acc[1] += qv * w4.y;
            acc[2] += qv * w4.z; acc[3] += qv * w4.w;
        }
    }
    int bglob = bg * 16 + bl;
#pragma unroll
    for (int j = 0; j < 4; ++j) {
        int c = cq + j;
        g_fq[bglob * 256 + h * 64 + c] = silu_f(acc[j] + g_bq[h * DD2 + c]);
    }
}

// ---------------- HMMA main kernel: one CTA per (b,h), 2 CTAs/SM ----------------
// bf16x2 split, 3 passes (a0b0, a0b1, a1b0); a1b1 (~2^-16 rel) dropped.
// A tiled 80/80/40 rows; online softmax in v-warps; 8 warps = 4 ng(n32) x 2 mg.
#define AS_SPL 20480
#define BS_OFF 40960
#define BS_SPL 32768
#define SCR_OFF 106496
#define SMEM_BYTES 108544

template<int MT>
__device__ __forceinline__ void gemm32(uint32_t sbase, int nb, int mbase, int lane, float d[][16]) {
#pragma unroll
    for (int mt = 0; mt < MT; ++mt)
#pragma unroll
        for (int i = 0; i < 16; ++i) d[mt][i] = 0.f;

    const uint32_t xr = (uint32_t)(lane & 7);
    const uint32_t arow = (uint32_t)(mbase + (lane & 15)) * 256;
    const uint32_t achk = (uint32_t)(lane >> 4);
    const uint32_t bl7 = (uint32_t)(lane & 7);
    const uint32_t bchk = (uint32_t)((lane >> 3) & 1);

#pragma unroll 1
    for (int ks = 0; ks < 8; ++ks) {
        uint32_t bf[2][4][2];
        const uint32_t bx = (((uint32_t)(2 * ks) + bchk) ^ xr) * 16;
#pragma unroll
        for (int s = 0; s < 2; ++s)
#pragma unroll
            for (int j = 0; j < 4; ++j)
                ldm_x2(bf[s][j], sbase + BS_OFF + s * BS_SPL + (uint32_t)(nb + j * 8 + bl7) * 256 + bx);
        const uint32_t ax = (((uint32_t)(2 * ks) + achk) ^ xr) * 16;
#pragma unroll
        for (int mt = 0; mt < MT; ++mt) {
            const uint32_t aoff = arow + (uint32_t)(mt * 16) * 256 + ax;
            uint32_t a0[4], a1[4];
            ldm_x4(a0, sbase + aoff);
            ldm_x4(a1, sbase + AS_SPL + aoff);
#pragma unroll
            for (int j = 0; j < 4; ++j) {
                mma16816(d[mt] + 4 * j, a0, bf[0][j]);
                mma16816(d[mt] + 4 * j, a0, bf[1][j]);
                mma16816(d[mt] + 4 * j, a1, bf[0][j]);
            }
        }
    }
}

__global__ __launch_bounds__(256, 2) void mha_hmma_kernel(
    const int* __restrict__ mask, const float* __restrict__ mm,
    const float* __restrict__ tau1, const float* __restrict__ tau2,
    float* __restrict__ out)
{
    extern __shared__ char smem[];
    float* scr = reinterpret_cast<float*>(smem + SCR_OFF);
    float* pd0 = scr;          // [80]
    float* pd1 = scr + 80;     // [80]
    float* lg_s = scr + 160;   // [80]
    float* mo  = scr + 240;    // [2][64]
    float* mp  = scr + 368;    // [2][64]
    float* mS  = scr + 496;    // [4]

    const int tid  = threadIdx.x;
    const int w    = tid >> 5;
    const int lane = tid & 31;
    const int g    = lane >> 2;
    const int t4   = lane & 3;
    const int b = blockIdx.x >> 2;
    const int h = blockIdx.x & 3;
    const int ng = w & 3;
    const int mg = w >> 2;
    const int nb = ng * 32;
    const bool is_f = (ng < 2);
    const uint32_t sbase = smem_u32(smem);

    float bcv[8], fqv[8];
#pragma unroll
    for (int j = 0; j < 4; ++j) {
        int c = nb + j * 8 + t4 * 2;
        bcv[2 * j]     = g_bc[h * 128 + c];
        bcv[2 * j + 1] = g_bc[h * 128 + c + 1];
        if (is_f) {
            fqv[2 * j]     = g_fq[b * 256 + h * 64 + c];
            fqv[2 * j + 1] = g_fq[b * 256 + h * 64 + c + 1];
        } else { fqv[2 * j] = 0.f; fqv[2 * j + 1] = 0.f; }
    }

    const __nv_bfloat16* asrc0 = g_A0 + (long)b * 25600;
    const __nv_bfloat16* asrc1 = g_A1 + (long)b * 25600;

    // ---- stage B (both splits) + A tile0 (80 rows) ----
    {
        const __nv_bfloat16* bsrc[2] = {g_B0 + h * 16384, g_B1 + h * 16384};
#pragma unroll
        for (int it = 0; it < 16; ++it) {
            int idx = tid + it * 256;          // < 4096
            int s = idx >> 11, r = idx & 2047;
            int crow = r >> 4, c = r & 15;
            uint32_t dst = sbase + BS_OFF + s * BS_SPL + crow * 256 + ((c ^ (crow & 7)) * 16);
            cp16(dst, bsrc[s] + crow * 128 + c * 8);
        }
#pragma unroll
        for (int it = 0; it < 10; ++it) {
            int idx = tid + it * 256;          // < 2560
            int s = idx / 1280;
            int r = idx - s * 1280;
            int l = r >> 4, c = r & 15;
            uint32_t dst = sbase + s * AS_SPL + l * 256 + ((c ^ (l & 7)) * 16);
            const __nv_bfloat16* src = (s == 0 ? asrc0 : asrc1) + (long)l * 128 + c * 8;
            cp16(dst, src);
        }
        CP_COMMIT(); CP_WAIT0();
    }
    __syncthreads();

    const float t1a = tau1[h], t1b = tau1[4 + h];
    const float cb1v = tau2[h], cb2v = tau2[4 + h], cb3v = tau2[8 + h];

    float m_run = -FLT_MAX, S_run = 0.f;
    float ov[8], pv[8];
#pragma unroll
    for (int i = 0; i < 8; ++i) { ov[i] = 0.f; pv[i] = 0.f; }

#pragma unroll 1
    for (int t = 0; t < 3; ++t) {
        const int tbase = t * 80;
        const int rowbase = (t < 2) ? (mg ? 48 : 0) : (mg ? 32 : 0);
        const int MT = (t < 2) ? (mg ? 2 : 3) : (mg ? 1 : 2);
        const int rows_t = (t < 2) ? 80 : 40;

        float d[3][16];
        if (t < 2) { if (mg == 0) gemm32<3>(sbase, nb, rowbase, lane, d);
                     else         gemm32<2>(sbase, nb, rowbase, lane, d); }
        else       { if (mg == 0) gemm32<2>(sbase, nb, rowbase, lane, d);
                     else         gemm32<1>(sbase, nb, rowbase, lane, d); }

        if (is_f) {
#pragma unroll
            for (int mt = 0; mt < 3; ++mt) {
                if (mt < MT) {
                    float s0 = 0.f, s1 = 0.f;
#pragma unroll
                    for (int j = 0; j < 4; ++j) {
                        s0 += silu_f(d[mt][4*j]   + bcv[2*j])   * fqv[2*j]
                            + silu_f(d[mt][4*j+1] + bcv[2*j+1]) * fqv[2*j+1];
                        s1 += silu_f(d[mt][4*j+2] + bcv[2*j])   * fqv[2*j]
                            + silu_f(d[mt][4*j+3] + bcv[2*j+1]) * fqv[2*j+1];
                    }
                    s0 += __shfl_xor_sync(0xffffffffu, s0, 1); s0 += __shfl_xor_sync(0xffffffffu, s0, 2);
                    s1 += __shfl_xor_sync(0xffffffffu, s1, 1); s1 += __shfl_xor_sync(0xffffffffu, s1, 2);
                    if (t4 == 0) {
                        float* pdp = (ng == 0) ? pd0 : pd1;
                        pdp[rowbase + mt * 16 + g]     = s0;
                        pdp[rowbase + mt * 16 + g + 8] = s1;
                    }
                }
            }
        }
        __syncthreads();   // A(t) fully consumed; pd visible

        if (t < 2) {
            const int ntb = tbase + 80;
            const int R = (t == 0) ? 80 : 40;
            const int chunks = R * 16;
            for (int idx = tid; idx < 2 * chunks; idx += 256) {
                int s = idx / chunks;
                int r = idx - s * chunks;
                int l = r >> 4, c = r & 15;
                uint32_t dst = sbase + s * AS_SPL + l * 256 + ((c ^ (l & 7)) * 16);
                const __nv_bfloat16* src = (s == 0 ? asrc0 : asrc1) + (long)(ntb + l) * 128 + c * 8;
                cp16(dst, src);
            }
            CP_COMMIT();
        }

        if (tid < rows_t) {
            int l = tbase + tid;
            float dd = pd0[tid] + pd1[tid];
            float mk = (float)mask[b * 200 + l];
            dd += (-1e9f) * (1.f - mk);
            float bias = mm[b * 200 + l] / t1a + mm[204800 + b * 200 + l] / t1b;
            lg_s[tid] = cb1v * dd + cb2v * bias + cb3v * dd * bias;
        }
        __syncthreads();

        if (!is_f) {
#pragma unroll
            for (int mt = 0; mt < 3; ++mt) {
                if (mt < MT) {
                    int loc0 = rowbase + mt * 16 + g;
#pragma unroll
                    for (int half = 0; half < 2; ++half) {
                        int loc = loc0 + half * 8;
                        int l = tbase + loc;
                        if (l < 200) {
                            float lg = lg_s[loc];
                            float mn = fmaxf(m_run, lg);
                            float sc = __expf(m_run - mn);
                            float e  = __expf(lg - mn);
                            S_run = S_run * sc + e;
#pragma unroll
                            for (int j = 0; j < 4; ++j) {
                                float v0 = silu_f(d[mt][4*j + 2*half]     + bcv[2*j]);
                                float v1 = silu_f(d[mt][4*j + 2*half + 1] + bcv[2*j+1]);
                                ov[2*j]   = ov[2*j]   * sc + e * v0;  pv[2*j]   += v0;
                                ov[2*j+1] = ov[2*j+1] * sc + e * v1;  pv[2*j+1] += v1;
                            }
                            m_run = mn;
                        }
                    }
                }
            }
        }
        if (t < 2) CP_WAIT0();
        __syncthreads();
    }

    // ---- merge ----
    if (!is_f) {
#pragma unroll
        for (int off = 4; off <= 16; off <<= 1) {
            float m2 = __shfl_xor_sync(0xffffffffu, m_run, off);
            float S2 = __shfl_xor_sync(0xffffffffu, S_run, off);
            float M = fmaxf(m_run, m2);
            float sa = __expf(m_run - M), sb = __expf(m2 - M);
            S_run = S_run * sa + S2 * sb;
#pragma unroll
            for (int i = 0; i < 8; ++i) {
                float o2 = __shfl_xor_sync(0xffffffffu, ov[i], off);
                float p2 = __shfl_xor_sync(0xffffffffu, pv[i], off);
                ov[i] = ov[i] * sa + o2 * sb;
                pv[i] += p2;
            }
            m_run = M;
        }
        if (lane < 4) {
#pragma unroll
            for (int j = 0; j < 4; ++j) {
                int c = (ng - 2) * 32 + j * 8 + t4 * 2;
                mo[mg * 64 + c]     = ov[2*j];
                mo[mg * 64 + c + 1] = ov[2*j+1];
                mp[mg * 64 + c]     = pv[2*j];
                mp[mg * 64 + c + 1] = pv[2*j+1];
            }
            if (ng == 2 && lane == 0) { mS[mg] = m_run; mS[2 + mg] = S_run; }
        }
    }
    __syncthreads();

    if (tid < 64) {
        float m0 = mS[0], m1 = mS[1];
        float M = fmaxf(m0, m1);
        float e0 = __expf(m0 - M), e1 = __expf(m1 - M);
        float S = mS[2] * e0 + mS[3] * e1;
        float o = mo[tid] * e0 + mo[64 + tid] * e1;
        float p = mp[tid] + mp[64 + tid];
        out[b * 256 + h * 64 + tid] = __fdividef(o, S) + 1e-7f * p;
    }
}

extern "C" void kernel_launch(void* const* d_in, const int* in_sizes, int n_in,
                              void* d_out, int out_size) {
    const float* query = (const float*)d_in[0];
    const float* fact  = (const float*)d_in[1];
    const int*   mask  = (const int*)  d_in[2];
    const float* mm    = (const float*)d_in[3];
    const float* Wq1   = (const float*)d_in[4];
    const float* bq1   = (const float*)d_in[5];
    const float* Wq2   = (const float*)d_in[6];
    const float* bq2   = (const float*)d_in[7];
    const float* Wf1   = (const float*)d_in[8];
    const float* bf1   = (const float*)d_in[9];
    const float* Wf2   = (const float*)d_in[10];
    const float* bf2   = (const float*)d_in[11];
    const float* Wv1   = (const float*)d_in[12];
    const float* bv1   = (const float*)d_in[13];
    const float* Wv2   = (const float*)d_in[14];
    const float* bv2   = (const float*)d_in[15];
    const float* tau1  = (const float*)d_in[16];
    const float* tau2  = (const float*)d_in[17];
    float* out = (float*)d_out;

    cudaFuncSetAttribute(mha_hmma_kernel, cudaFuncAttributeMaxDynamicSharedMemorySize, SMEM_BYTES);

    collapse_q_kernel<<<512, 256>>>(Wq1, bq1, Wq2, bq2);
    collapse_fvT_kernel<<<256, 256>>>(Wf1, bf1, Wf2, bf2, Wv1, bv1, Wv2, bv2);
    presplit_fact<<<12800, 256>>>(fact);
    fq_kernel<<<256, 256>>>(query);
    mha_hmma_kernel<<<BB * HH, 256, SMEM_BYTES>>>(mask, mm, tau1, tau2, out);
}

// round 14
// speedup vs baseline: 1.6066x; 1.0172x over previous
#include <cuda_runtime.h>
#include <cuda_bf16.h>
#include <float.h>
#include <stdint.h>

#define HH 4
#define BB 1024
#define DQv 512
#define DFv 128
#define DD1 128
#define DD2 64

__device__ float g_Wq[HH * DQv * DD2];
__device__ float g_bq[HH * DD2];
__device__ float g_bc[HH * 128];
__device__ float g_fq[BB * HH * DD2];
__device__ __nv_bfloat16 g_B0[HH * 128 * 128];   // [h][c][k]
__device__ __nv_bfloat16 g_B1[HH * 128 * 128];
__device__ __nv_bfloat16 g_A0[(long)BB * 200 * 128];  // [b][l][k]
__device__ __nv_bfloat16 g_A1[(long)BB * 200 * 128];

__device__ __forceinline__ float silu_f(float x) { return __fdividef(x, 1.f + __expf(-x)); }
__device__ __forceinline__ uint32_t smem_u32(const void* p) {
    uint32_t a;
    asm("{ .reg .u64 t; cvta.to.shared.u64 t, %1; cvt.u32.u64 %0, t; }" : "=r"(a) : "l"(p));
    return a;
}
__device__ __forceinline__ uint32_t bf2pack(float lo, float hi) {
    uint32_t r;
    asm("cvt.rn.bf16x2.f32 %0, %1, %2;" : "=r"(r) : "f"(hi), "f"(lo));
    return r;
}
__device__ __forceinline__ float bflo(uint32_t q) { return __uint_as_float(q << 16); }
__device__ __forceinline__ float bfhi(uint32_t q) { return __uint_as_float(q & 0xffff0000u); }

__device__ __forceinline__ void ldm_x4(uint32_t a[4], uint32_t addr) {
    asm volatile("ldmatrix.sync.aligned.m8n8.x4.shared.b16 {%0,%1,%2,%3}, [%4];"
        : "=r"(a[0]), "=r"(a[1]), "=r"(a[2]), "=r"(a[3]) : "r"(addr));
}
__device__ __forceinline__ void mma16816(float d[4], const uint32_t a[4], const uint32_t b[2]) {
    asm volatile(
        "mma.sync.aligned.m16n8k16.row.col.f32.bf16.bf16.f32 "
        "{%0,%1,%2,%3}, {%4,%5,%6,%7}, {%8,%9}, {%0,%1,%2,%3};"
        : "+f"(d[0]), "+f"(d[1]), "+f"(d[2]), "+f"(d[3])
        : "r"(a[0]), "r"(a[1]), "r"(a[2]), "r"(a[3]), "r"(b[0]), "r"(b[1]));
}
__device__ __forceinline__ void cp16(uint32_t dst, const void* src) {
    asm volatile("cp.async.cg.shared.global [%0], [%1], 16;" :: "r"(dst), "l"(src));
}
#define CP_COMMIT()      asm volatile("cp.async.commit_group;" ::: "memory")
#define CP_WAIT0()       asm volatile("cp.async.wait_group 0;" ::: "memory")

// ---------------- prekernels ----------------
__global__ void collapse_q_kernel(const float* __restrict__ Wq1, const float* __restrict__ bq1,
                                  const float* __restrict__ Wq2, const float* __restrict__ bq2) {
    int idx = blockIdx.x * 256 + threadIdx.x;
    int c = idx & 63, k = (idx >> 6) & 511, h = idx >> 15;
    const float* a  = Wq1 + (h * DQv + k) * DD1;
    const float* w2 = Wq2 + h * DD1 * DD2 + c;
    float acc = 0.f;
#pragma unroll 8
    for (int j = 0; j < DD1; ++j) acc += a[j] * w2[j * DD2];
    g_Wq[idx] = acc;
    if (k == 0) {
        float bb = bq2[h * DD2 + c];
        const float* b1p = bq1 + h * DD1;
#pragma unroll 8
        for (int j = 0; j < DD1; ++j) bb += b1p[j] * w2[j * DD2];
        g_bq[h * DD2 + c] = bb;
    }
}

__global__ void collapse_fvT_kernel(const float* __restrict__ Wf1, const float* __restrict__ bf1,
                                    const float* __restrict__ Wf2, const float* __restrict__ bf2,
                                    const float* __restrict__ Wv1, const float* __restrict__ bv1,
                                    const float* __restrict__ Wv2, const float* __restrict__ bv2) {
    int idx = blockIdx.x * 256 + threadIdx.x;
    int c = idx & 127, k = (idx >> 7) & 127, h = idx >> 14;
    const float *W1, *W2, *B1, *B2; int cc;
    if (c < 64) { W1 = Wf1; W2 = Wf2; B1 = bf1; B2 = bf2; cc = c; }
    else        { W1 = Wv1; W2 = Wv2; B1 = bv1; B2 = bv2; cc = c - 64; }
    const float* a  = W1 + (h * DFv + k) * DD1;
    const float* w2 = W2 + h * DD1 * DD2 + cc;
    float acc = 0.f;
#pragma unroll 8
    for (int j = 0; j < DD1; ++j) acc += a[j] * w2[j * DD2];
    int o = h * 16384 + c * 128 + k;
    __nv_bfloat16 q0 = __float2bfloat16(acc);
    float r1 = acc - __bfloat162float(q0);
    g_B0[o] = q0; g_B1[o] = __float2bfloat16(r1);
    if (k == 0) {
        float bb = B2[h * DD2 + cc];
        const float* b1p = B1 + h * DD1;
#pragma unroll 8
        for (int j = 0; j < DD1; ++j) bb += b1p[j] * w2[j * DD2];
        g_bc[h * 128 + c] = bb;
    }
}

__global__ __launch_bounds__(256) void presplit_fact(const float* __restrict__ fact) {
    long idx = (long)blockIdx.x * 256 + threadIdx.x;
    long base = idx * 8;
    float xv[8];
    *reinterpret_cast<float4*>(xv)     = *reinterpret_cast<const float4*>(fact + base);
    *reinterpret_cast<float4*>(xv + 4) = *reinterpret_cast<const float4*>(fact + base + 4);
    uint32_t p0[4], p1[4];
#pragma unroll
    for (int i = 0; i < 4; ++i) {
        float lo = xv[2 * i], hi = xv[2 * i + 1];
        uint32_t q0 = bf2pack(lo, hi);
        float rlo = lo - bflo(q0), rhi = hi - bfhi(q0);
        p0[i] = q0; p1[i] = bf2pack(rlo, rhi);
    }
    *reinterpret_cast<uint4*>(reinterpret_cast<char*>(g_A0) + base * 2) = make_uint4(p0[0], p0[1], p0[2], p0[3]);
    *reinterpret_cast<uint4*>(reinterpret_cast<char*>(g_A1) + base * 2) = make_uint4(p1[0], p1[1], p1[2], p1[3]);
}

// fq: grid 128 (32 bg x 4 h); block tile 32 b x 64 c; thread = 2b x 4c
__global__ __launch_bounds__(256) void fq_kernel(const float* __restrict__ query) {
    __shared__ float qs[32 * 66];
    __shared__ float ws[64 * 64];
    const int tid = threadIdx.x;
    const int h  = blockIdx.x & 3;
    const int bg = blockIdx.x >> 2;
    const int bl = (tid >> 4) * 2;     // 2 rows
    const int cq = (tid & 15) * 4;     // 4 cols
    float acc[8];
#pragma unroll
    for (int i = 0; i < 8; ++i) acc[i] = 0.f;
    for (int kc = 0; kc < 8; ++kc) {
        __syncthreads();
#pragma unroll
        for (int it = 0; it < 8; ++it) {
            int idx = tid + it * 256;          // < 2048
            int bb = idx >> 6, kk = idx & 63;
            qs[bb * 66 + kk] = query[(long)(bg * 32 + bb) * DQv + kc * 64 + kk];
        }
#pragma unroll
        for (int it = 0; it < 16; ++it) {
            int idx = tid + it * 256;
            ws[idx] = g_Wq[(h * DQv + kc * 64 + (idx >> 6)) * DD2 + (idx & 63)];
        }
        __syncthreads();
#pragma unroll 4
        for (int k = 0; k < 64; ++k) {
            float qv0 = qs[bl * 66 + k];
            float qv1 = qs[(bl + 1) * 66 + k];
            float4 w4 = *reinterpret_cast<const float4*>(ws + k * 64 + cq);
            acc[0] += qv0 * w4.x; acc[1] += qv0 * w4.y;
            acc[2] += qv0 * w4.z; acc[3] += qv0 * w4.w;
            acc[4] += qv1 * w4.x; acc[5] += qv1 * w4.y;
            acc[6] += qv1 * w4.z; acc[7] += qv1 * w4.w;
        }
    }
    int bglob = bg * 32 + bl;
#pragma unroll
    for (int r = 0; r < 2; ++r)
#pragma unroll
        for (int j = 0; j < 4; ++j) {
            int c = cq + j;
            g_fq[(bglob + r) * 256 + h * 64 + c] = silu_f(acc[r * 4 + j] + g_bq[h * DD2 + c]);
        }
}

// ---------------- HMMA main kernel: one CTA per (b,h), 2 CTAs/SM ----------------
// bf16x2 split, 3 passes (a0b0, a0b1, a1b0).
// A tiled 80/80/40; online softmax in v-warps; 8 warps = 4 ng(n32) x 2 mg.
#define AS_SPL 20480
#define BS_OFF 40960
#define BS_SPL 32768
#define SCR_OFF 106496
#define SMEM_BYTES 108544

template<int MT>
__device__ __forceinline__ void gemm32(uint32_t sbase, int nb, int mbase, int lane, float d[][16]) {
#pragma unroll
    for (int mt = 0; mt < MT; ++mt)
#pragma unroll
        for (int i = 0; i < 16; ++i) d[mt][i] = 0.f;

    const uint32_t xr = (uint32_t)(lane & 7);
    const uint32_t arow = (uint32_t)(mbase + (lane & 15)) * 256;
    const uint32_t achk = (uint32_t)(lane >> 4);
    // B x4 addressing: lanes 0-7 -> (jpair*2+0, k-lo), 8-15 -> (jpair*2+0, k-hi),
    //                  16-23 -> (jpair*2+1, k-lo), 24-31 -> (jpair*2+1, k-hi)
    const uint32_t bj  = (uint32_t)(lane >> 4);          // j within pair
    const uint32_t bchk = (uint32_t)((lane >> 3) & 1);
    const uint32_t brow_base = (uint32_t)(nb + bj * 8 + (lane & 7)) * 256;

#pragma unroll 1
    for (int ks = 0; ks < 8; ++ks) {
        uint32_t bf[2][2][4];   // [split][jpair][4 regs = frag j(2) + frag j+1(2)]
        const uint32_t bx = (((uint32_t)(2 * ks) + bchk) ^ xr) * 16;
#pragma unroll
        for (int s = 0; s < 2; ++s)
#pragma unroll
            for (int jp = 0; jp < 2; ++jp)
                ldm_x4(bf[s][jp], sbase + BS_OFF + s * BS_SPL + brow_base + (uint32_t)(jp * 16) * 256 + bx);
        const uint32_t ax = (((uint32_t)(2 * ks) + achk) ^ xr) * 16;
#pragma unroll
        for (int mt = 0; mt < MT; ++mt) {
            const uint32_t aoff = arow + (uint32_t)(mt * 16) * 256 + ax;
            uint32_t a0[4], a1[4];
            ldm_x4(a0, sbase + aoff);
            ldm_x4(a1, sbase + AS_SPL + aoff);
#pragma unroll
            for (int jp = 0; jp < 2; ++jp)
#pragma unroll
                for (int jj = 0; jj < 2; ++jj) {
                    int j = jp * 2 + jj;
                    mma16816(d[mt] + 4 * j, a0, bf[0][jp] + 2 * jj);
                    mma16816(d[mt] + 4 * j, a0, bf[1][jp] + 2 * jj);
                    mma16816(d[mt] + 4 * j, a1, bf[0][jp] + 2 * jj);
                }
        }
    }
}

__global__ __launch_bounds__(256, 2) void mha_hmma_kernel(
    const int* __restrict__ mask, const float* __restrict__ mm,
    const float* __restrict__ tau1, const float* __restrict__ tau2,
    float* __restrict__ out)
{
    extern __shared__ char smem[];
    float* scr = reinterpret_cast<float*>(smem + SCR_OFF);
    float* pd0 = scr;          // [80]
    float* pd1 = scr + 80;     // [80]
    float* lg_s = scr + 160;   // [80]
    float* mo  = scr + 240;    // [2][64]
    float* mp  = scr + 368;    // [2][64]
    float* mS  = scr + 496;    // [4]

    const int tid  = threadIdx.x;
    const int w    = tid >> 5;
    const int lane = tid & 31;
    const int g    = lane >> 2;
    const int t4   = lane & 3;
    const int b = blockIdx.x >> 2;
    const int h = blockIdx.x & 3;
    const int ng = w & 3;
    const int mg = w >> 2;
    const int nb = ng * 32;
    const bool is_f = (ng < 2);
    const uint32_t sbase = smem_u32(smem);

    float bcv[8], fqv[8];
#pragma unroll
    for (int j = 0; j < 4; ++j) {
        int c = nb + j * 8 + t4 * 2;
        bcv[2 * j]     = g_bc[h * 128 + c];
        bcv[2 * j + 1] = g_bc[h * 128 + c + 1];
        if (is_f) {
            fqv[2 * j]     = g_fq[b * 256 + h * 64 + c];
            fqv[2 * j + 1] = g_fq[b * 256 + h * 64 + c + 1];
        } else { fqv[2 * j] = 0.f; fqv[2 * j + 1] = 0.f; }
    }

    const __nv_bfloat16* asrc0 = g_A0 + (long)b * 25600;
    const __nv_bfloat16* asrc1 = g_A1 + (long)b * 25600;

    // ---- stage B (both splits) + A tile0 (80 rows) ----
    {
        const __nv_bfloat16* bsrc[2] = {g_B0 + h * 16384, g_B1 + h * 16384};
#pragma unroll
        for (int it = 0; it < 16; ++it) {
            int idx = tid + it * 256;          // < 4096
            int s = idx >> 11, r = idx & 2047;
            int crow = r >> 4, c = r & 15;
            uint32_t dst = sbase + BS_OFF + s * BS_SPL + crow * 256 + ((c ^ (crow & 7)) * 16);
            cp16(dst, bsrc[s] + crow * 128 + c * 8);
        }
#pragma unroll
        for (int it = 0; it < 10; ++it) {
            int idx = tid + it * 256;          // < 2560
            int s = idx / 1280;
            int r = idx - s * 1280;
            int l = r >> 4, c = r & 15;
            uint32_t dst = sbase + s * AS_SPL + l * 256 + ((c ^ (l & 7)) * 16);
            const __nv_bfloat16* src = (s == 0 ? asrc0 : asrc1) + (long)l * 128 + c * 8;
            cp16(dst, src);
        }
        CP_COMMIT(); CP_WAIT0();
    }
    __syncthreads();

    const float t1a = tau1[h], t1b = tau1[4 + h];
    const float cb1v = tau2[h], cb2v = tau2[4 + h], cb3v = tau2[8 + h];

    float m_run = -FLT_MAX, S_run = 0.f;
    float ov[8], pv[8];
#pragma unroll
    for (int i = 0; i < 8; ++i) { ov[i] = 0.f; pv[i] = 0.f; }

#pragma unroll 1
    for (int t = 0; t < 3; ++t) {
        const int tbase = t * 80;
        const int rowbase = (t < 2) ? (mg ? 48 : 0) : (mg ? 32 : 0);
        const int MT = (t < 2) ? (mg ? 2 : 3) : (mg ? 1 : 2);
        const int rows_t = (t < 2) ? 80 : 40;

        float d[3][16];
        if (t < 2) { if (mg == 0) gemm32<3>(sbase, nb, rowbase, lane, d);
                     else         gemm32<2>(sbase, nb, rowbase, lane, d); }
        else       { if (mg == 0) gemm32<2>(sbase, nb, rowbase, lane, d);
                     else         gemm32<1>(sbase, nb, rowbase, lane, d); }

        if (is_f) {
#pragma unroll
            for (int mt = 0; mt < 3; ++mt) {
                if (mt < MT) {
                    float s0 = 0.f, s1 = 0.f;
#pragma unroll
                    for (int j = 0; j < 4; ++j) {
                        s0 += silu_f(d[mt][4*j]   + bcv[2*j])   * fqv[2*j]
                            + silu_f(d[mt][4*j+1] + bcv[2*j+1]) * fqv[2*j+1];
                        s1 += silu_f(d[mt][4*j+2] + bcv[2*j])   * fqv[2*j]
                            + silu_f(d[mt][4*j+3] + bcv[2*j+1]) * fqv[2*j+1];
                    }
                    s0 += __shfl_xor_sync(0xffffffffu, s0, 1); s0 += __shfl_xor_sync(0xffffffffu, s0, 2);
                    s1 += __shfl_xor_sync(0xffffffffu, s1, 1); s1 += __shfl_xor_sync(0xffffffffu, s1, 2);
                    if (t4 == 0) {
                        float* pdp = (ng == 0) ? pd0 : pd1;
                        pdp[rowbase + mt * 16 + g]     = s0;
                        pdp[rowbase + mt * 16 + g + 8] = s1;
                    }
                }
            }
        }
        __syncthreads();   // A(t) fully consumed; pd visible

        if (t < 2) {
            const int ntb = tbase + 80;
            const int R = (t == 0) ? 80 : 40;
            const int chunks = R * 16;
            for (int idx = tid; idx < 2 * chunks; idx += 256) {
                int s = idx / chunks;
                int r = idx - s * chunks;
                int l = r >> 4, c = r & 15;
                uint32_t dst = sbase + s * AS_SPL + l * 256 + ((c ^ (l & 7)) * 16);
                const __nv_bfloat16* src = (s == 0 ? asrc0 : asrc1) + (long)(ntb + l) * 128 + c * 8;
                cp16(dst, src);
            }
            CP_COMMIT();
        }

        if (tid < rows_t) {
            int l = tbase + tid;
            float dd = pd0[tid] + pd1[tid];
            float mk = (float)mask[b * 200 + l];
            dd += (-1e9f) * (1.f - mk);
            float bias = mm[b * 200 + l] / t1a + mm[204800 + b * 200 + l] / t1b;
            lg_s[tid] = cb1v * dd + cb2v * bias + cb3v * dd * bias;
        }
        __syncthreads();

        if (!is_f) {
#pragma unroll
            for (int mt = 0; mt < 3; ++mt) {
                if (mt < MT) {
                    int loc0 = rowbase + mt * 16 + g;
#pragma unroll
                    for (int half = 0; half < 2; ++half) {
                        int loc = loc0 + half * 8;
                        int l = tbase + loc;
                        if (l < 200) {
                            float lg = lg_s[loc];
                            float mn = fmaxf(m_run, lg);
                            float sc = __expf(m_run - mn);
                            float e  = __expf(lg - mn);
                            S_run = S_run * sc + e;
#pragma unroll
                            for (int j = 0; j < 4; ++j) {
                                float v0 = silu_f(d[mt][4*j + 2*half]     + bcv[2*j]);
                                float v1 = silu_f(d[mt][4*j + 2*half + 1] + bcv[2*j+1]);
                                ov[2*j]   = ov[2*j]   * sc + e * v0;  pv[2*j]   += v0;
                                ov[2*j+1] = ov[2*j+1] * sc + e * v1;  pv[2*j+1] += v1;
                            }
                            m_run = mn;
                        }
                    }
                }
            }
        }
        if (t < 2) CP_WAIT0();
        __syncthreads();
    }

    // ---- merge ----
    if (!is_f) {
#pragma unroll
        for (int off = 4; off <= 16; off <<= 1) {
            float m2 = __shfl_xor_sync(0xffffffffu, m_run, off);
            float S2 = __shfl_xor_sync(0xffffffffu, S_run, off);
            float M = fmaxf(m_run, m2);
            float sa = __expf(m_run - M), sb = __expf(m2 - M);
            S_run = S_run * sa + S2 * sb;
#pragma unroll
            for (int i = 0; i < 8; ++i) {
                float o2 = __shfl_xor_sync(0xffffffffu, ov[i], off);
                float p2 = __shfl_xor_sync(0xffffffffu, pv[i], off);
                ov[i] = ov[i] * sa + o2 * sb;
                pv[i] += p2;
            }
            m_run = M;
        }
        if (lane < 4) {
#pragma unroll
            for (int j = 0; j < 4; ++j) {
                int c = (ng - 2) * 32 + j * 8 + t4 * 2;
                mo[mg * 64 + c]     = ov[2*j];
                mo[mg * 64 + c + 1] = ov[2*j+1];
                mp[mg * 64 + c]     = pv[2*j];
                mp[mg * 64 + c + 1] = pv[2*j+1];
            }
            if (ng == 2 && lane == 0) { mS[mg] = m_run; mS[2 + mg] = S_run; }
        }
    }
    __syncthreads();

    if (tid < 64) {
        float m0 = mS[0], m1 = mS[1];
        float M = fmaxf(m0, m1);
        float e0 = __expf(m0 - M), e1 = __expf(m1 - M);
        float S = mS[2] * e0 + mS[3] * e1;
        float o = mo[tid] * e0 + mo[64 + tid] * e1;
        float p = mp[tid] + mp[64 + tid];
        out[b * 256 + h * 64 + tid] = __fdividef(o, S) + 1e-7f * p;
    }
}

extern "C" void kernel_launch(void* const* d_in, const int* in_sizes, int n_in,
                              void* d_out, int out_size) {
    const float* query = (const float*)d_in[0];
    const float* fact  = (const float*)d_in[1];
    const int*   mask  = (const int*)  d_in[2];
    const float* mm    = (const float*)d_in[3];
    const float* Wq1   = (const float*)d_in[4];
    const float* bq1   = (const float*)d_in[5];
    const float* Wq2   = (const float*)d_in[6];
    const float* bq2   = (const float*)d_in[7];
    const float* Wf1   = (const float*)d_in[8];
    const float* bf1   = (const float*)d_in[9];
    const float* Wf2   = (const float*)d_in[10];
    const float* bf2   = (const float*)d_in[11];
    const float* Wv1   = (const float*)d_in[12];
    const float* bv1   = (const float*)d_in[13];
    const float* Wv2   = (const float*)d_in[14];
    const float* bv2   = (const float*)d_in[15];
    const float* tau1  = (const float*)d_in[16];
    const float* tau2  = (const float*)d_in[17];
    float* out = (float*)d_out;

    cudaFuncSetAttribute(mha_hmma_kernel, cudaFuncAttributeMaxDynamicSharedMemorySize, SMEM_BYTES);

    collapse_q_kernel<<<512, 256>>>(Wq1, bq1, Wq2, bq2);
    collapse_fvT_kernel<<<256, 256>>>(Wf1, bf1, Wf2, bf2, Wv1, bv1, Wv2, bv2);
    presplit_fact<<<12800, 256>>>(fact);
    fq_kernel<<<128, 256>>>(query);
    mha_hmma_kernel<<<BB * HH, 256, SMEM_BYTES>>>(mask, mm, tau1, tau2, out);
}